// round 14
// baseline (speedup 1.0000x reference)
#include <cuda_runtime.h>
#include <cuda_fp16.h>
#include <cstdint>
#include <math.h>

// ---------------- problem dims ----------------
#define Bb   8
#define Ss   2048
#define RR   (Bb*Ss)       // 16384 rows
#define DIN  1024
#define HH   2048
#define KK   256
#define DM   512
#define DOUT 1024
#define BANKN 4096
#define SEGL 128
#define NSEG (Ss/SEGL)     // 16
#define RISK_EPS 3e-4f

// ---------------- device scratch (static, allowed) ----------------
__device__ __half   d_xhi[(size_t)RR*DIN];
__device__ __half   d_xlo[(size_t)RR*DIN];
__device__ __half   d_hhi[(size_t)RR*HH];      // 67 MB
__device__ __half   d_hlo[(size_t)RR*HH];      // 67 MB
__device__ __half   d_WtrThi[(size_t)HH*DIN];
__device__ __half   d_WtrTlo[(size_t)HH*DIN];
__device__ __half   d_WmsThi[(size_t)KK*HH];
__device__ __half   d_WmsTlo[(size_t)KK*HH];
__device__ float    d_WtrT32[(size_t)HH*DIN];  // fp32 transposed weights (exact path)
__device__ float    d_WmsT32[(size_t)KK*HH];
__device__ float    d_logits[(size_t)RR*KK];   // 16.8 MB
__device__ int      d_a0[RR];
__device__ unsigned d_keep[(size_t)RR*8];      // 256-bit keep masks
__device__ int      d_mode[RR];
__device__ int      d_exitv[Bb*NSEG*KK];
__device__ int      d_entry[Bb*NSEG];
__device__ int      d_risk[RR];
__device__ int      d_nrisk;
__device__ float    d_knT[(size_t)DM*BANKN];   // normalized bank keys [DM,BANK]
__device__ float    d_qn[KK*DM];
__device__ float    d_scores[(size_t)KK*BANKN];
__device__ float    d_part[8*KK*DM];
__device__ float    d_bankt[KK*DM];
__device__ float    d_rn[KK*DM];
__device__ float    d_ytab[KK*DOUT];

// =======================================================================
// baseline-PTX helpers (all legal on compute_103)
// =======================================================================
__device__ __forceinline__ uint32_t smem_u32(const void* p){
    uint32_t a;
    asm("{ .reg .u64 t; cvta.to.shared.u64 t, %1; cvt.u32.u64 %0, t; }" : "=r"(a) : "l"(p));
    return a;
}
__device__ __forceinline__ void cpasync16(uint32_t dst, const void* src){
    asm volatile("cp.async.ca.shared.global [%0], [%1], 16;" :: "r"(dst), "l"(src));
}
#define CP_COMMIT() asm volatile("cp.async.commit_group;" ::: "memory")
#define CP_WAIT0()  asm volatile("cp.async.wait_group 0;" ::: "memory")

__device__ __forceinline__ void ldsm4(uint32_t* r, uint32_t addr){
    asm volatile("ldmatrix.sync.aligned.m8n8.x4.shared.b16 {%0,%1,%2,%3}, [%4];"
        : "=r"(r[0]), "=r"(r[1]), "=r"(r[2]), "=r"(r[3]) : "r"(addr));
}
__device__ __forceinline__ void mma16816(float* d, const uint32_t* a, const uint32_t* b){
    asm volatile("mma.sync.aligned.m16n8k16.row.col.f32.f16.f16.f32 "
        "{%0,%1,%2,%3}, {%4,%5,%6,%7}, {%8,%9}, {%0,%1,%2,%3};"
        : "+f"(d[0]), "+f"(d[1]), "+f"(d[2]), "+f"(d[3])
        : "r"(a[0]), "r"(a[1]), "r"(a[2]), "r"(a[3]), "r"(b[0]), "r"(b[1]));
}

// =======================================================================
// fp16-split (Markidis) tensor-core GEMM (same as R12, numerically verified)
// =======================================================================
#define BM 128
#define BN 128
#define BK 32
#define SSTR 40
#define TILEB (128*SSTR*2)
#define STAGEB (4*TILEB)
#define HSMEM (2*STAGEB)

__global__ void __launch_bounds__(256, 1) hgemm(
    const __half* __restrict__ Ahi, const __half* __restrict__ Alo,
    const __half* __restrict__ Bhi, const __half* __restrict__ Blo,
    const float* __restrict__ bias,
    float* __restrict__ Cf, __half* __restrict__ Chi, __half* __restrict__ Clo,
    int M, int Ntot, int K, int doRelu)
{
    extern __shared__ char sm[];
    const int tid  = threadIdx.x;
    const int lane = tid & 31;
    const int w    = tid >> 5;
    const int wm   = w & 3;
    const int wn   = w >> 2;
    const int bx = blockIdx.x, by = blockIdx.y;

    const uint32_t smb = smem_u32(sm);

    const __half* tb[4];
    tb[0] = Ahi + (size_t)(by*BM) * K;
    tb[1] = Alo + (size_t)(by*BM) * K;
    tb[2] = Bhi + (size_t)(bx*BN) * K;
    tb[3] = Blo + (size_t)(bx*BN) * K;

    float acc[2][8][4];
#pragma unroll
    for (int i = 0; i < 2; i++)
#pragma unroll
        for (int j = 0; j < 8; j++)
#pragma unroll
            for (int q = 0; q < 4; q++) acc[i][j][q] = 0.f;

    auto loadstage = [&](int st, int k0){
        uint32_t sb = smb + st * STAGEB;
#pragma unroll
        for (int m = 0; m < 4; m++) {
#pragma unroll
            for (int i = 0; i < 2; i++) {
                int idx = i*256 + tid;
                int row = idx >> 2, c4 = idx & 3;
                uint32_t dst = sb + m*TILEB + row*(SSTR*2) + c4*16;
                const __half* src = tb[m] + (size_t)row * K + k0 + c4*8;
                cpasync16(dst, src);
            }
        }
    };

    auto compute = [&](int st){
        uint32_t sA = smb + st * STAGEB;
        uint32_t sB = sA + 2*TILEB;
#pragma unroll
        for (int ks = 0; ks < 2; ks++) {
            uint32_t ahi[2][4], alo[2][4];
#pragma unroll
            for (int mt = 0; mt < 2; mt++) {
                int row  = wm*32 + mt*16 + (lane & 15);
                int koff = ks*16 + ((lane >> 4) << 3);
                uint32_t ad = sA + row*(SSTR*2) + koff*2;
                ldsm4(ahi[mt], ad);
                ldsm4(alo[mt], ad + TILEB);
            }
            uint32_t bhi[8][2], blo[8][2];
#pragma unroll
            for (int g = 0; g < 4; g++) {
                int nrow = wn*64 + g*16 + (lane & 7) + ((lane >> 4) << 3);
                int koff = ks*16 + (((lane >> 3) & 1) << 3);
                uint32_t bd = sB + nrow*(SSTR*2) + koff*2;
                uint32_t t4[4];
                ldsm4(t4, bd);
                bhi[2*g][0] = t4[0]; bhi[2*g][1] = t4[1];
                bhi[2*g+1][0] = t4[2]; bhi[2*g+1][1] = t4[3];
                ldsm4(t4, bd + TILEB);
                blo[2*g][0] = t4[0]; blo[2*g][1] = t4[1];
                blo[2*g+1][0] = t4[2]; blo[2*g+1][1] = t4[3];
            }
#pragma unroll
            for (int mt = 0; mt < 2; mt++)
#pragma unroll
                for (int nt = 0; nt < 8; nt++) {
                    mma16816(acc[mt][nt], ahi[mt], bhi[nt]);
                    mma16816(acc[mt][nt], ahi[mt], blo[nt]);
                    mma16816(acc[mt][nt], alo[mt], bhi[nt]);
                }
        }
    };

    const int NC = K / BK;
    loadstage(0, 0); CP_COMMIT();
    CP_WAIT0(); __syncthreads();
    for (int c = 0; c < NC; c++) {
        int cur = c & 1;
        if (c + 1 < NC) { loadstage(cur ^ 1, (c + 1) * BK); CP_COMMIT(); }
        compute(cur);
        if (c + 1 < NC) { CP_WAIT0(); __syncthreads(); }
    }

#pragma unroll
    for (int mt = 0; mt < 2; mt++) {
#pragma unroll
        for (int nt = 0; nt < 8; nt++) {
            int r0 = by*BM + wm*32 + mt*16 + (lane >> 2);
            int c0 = bx*BN + wn*64 + nt*8 + (lane & 3)*2;
            float b0 = bias ? bias[c0]   : 0.f;
            float b1 = bias ? bias[c0+1] : 0.f;
            float v0 = acc[mt][nt][0] + b0;
            float v1 = acc[mt][nt][1] + b1;
            float v2 = acc[mt][nt][2] + b0;
            float v3 = acc[mt][nt][3] + b1;
            if (doRelu) {
                v0 = fmaxf(v0, 0.f); v1 = fmaxf(v1, 0.f);
                v2 = fmaxf(v2, 0.f); v3 = fmaxf(v3, 0.f);
            }
            if (Cf) {
                *(float2*)(Cf + (size_t)r0 * Ntot + c0)       = make_float2(v0, v1);
                *(float2*)(Cf + (size_t)(r0+8) * Ntot + c0)   = make_float2(v2, v3);
            } else {
                __half h0 = __float2half_rn(v0), h1 = __float2half_rn(v1);
                __half h2 = __float2half_rn(v2), h3 = __float2half_rn(v3);
                __half l0 = __float2half_rn(v0 - __half2float(h0));
                __half l1 = __float2half_rn(v1 - __half2float(h1));
                __half l2 = __float2half_rn(v2 - __half2float(h2));
                __half l3 = __float2half_rn(v3 - __half2float(h3));
                *(__half2*)(Chi + (size_t)r0 * Ntot + c0)     = __halves2half2(h0, h1);
                *(__half2*)(Chi + (size_t)(r0+8) * Ntot + c0) = __halves2half2(h2, h3);
                *(__half2*)(Clo + (size_t)r0 * Ntot + c0)     = __halves2half2(l0, l1);
                *(__half2*)(Clo + (size_t)(r0+8) * Ntot + c0) = __halves2half2(l2, l3);
            }
        }
    }
}

// ---------------- fp32 -> fp16 hi/lo split ----------------
__global__ void split_k(const float* __restrict__ in, __half* __restrict__ hi,
                        __half* __restrict__ lo, int n)
{
    int i = (blockIdx.x * 256 + threadIdx.x) * 4;
    if (i >= n) return;
    float4 v = *(const float4*)(in + i);
    __half h0 = __float2half_rn(v.x), h1 = __float2half_rn(v.y);
    __half h2 = __float2half_rn(v.z), h3 = __float2half_rn(v.w);
    *(__half2*)(hi + i)     = __halves2half2(h0, h1);
    *(__half2*)(hi + i + 2) = __halves2half2(h2, h3);
    __half l0 = __float2half_rn(v.x - __half2float(h0));
    __half l1 = __float2half_rn(v.y - __half2float(h1));
    __half l2 = __float2half_rn(v.z - __half2float(h2));
    __half l3 = __float2half_rn(v.w - __half2float(h3));
    *(__half2*)(lo + i)     = __halves2half2(l0, l1);
    *(__half2*)(lo + i + 2) = __halves2half2(l2, l3);
}

// ---------------- transpose [R,C] fp32 -> [C,R] fp16 hi/lo + fp32 ----------------
__global__ void transpose_split_k(const float* __restrict__ in,
                                  __half* __restrict__ hi, __half* __restrict__ lo,
                                  float* __restrict__ f32out,
                                  int R, int C)
{
    __shared__ float t[32][33];
    int c0 = blockIdx.x * 32, r0 = blockIdx.y * 32;
    int x = threadIdx.x, y = threadIdx.y;
    for (int i = y; i < 32; i += 8) t[i][x] = in[(size_t)(r0 + i) * C + c0 + x];
    __syncthreads();
    for (int i = y; i < 32; i += 8) {
        float v = t[x][i];
        __half h = __float2half_rn(v);
        __half l = __float2half_rn(v - __half2float(h));
        size_t o = (size_t)(c0 + i) * R + r0 + x;
        hi[o] = h; lo[o] = l;
        f32out[o] = v;
    }
}

// ---------------- risk counter reset ----------------
__global__ void zero_nrisk_k() { if (threadIdx.x == 0) d_nrisk = 0; }

// ---------------- flag rows with near-tie decisions ----------------
__global__ void flag_k()
{
    int row = blockIdx.x * 8 + threadIdx.y;
    int lane = threadIdx.x;
    const float* lg = d_logits + (size_t)row * KK;
    float v[8];
    float best = -3.4e38f; int bi = 0;
#pragma unroll
    for (int t = 0; t < 8; t++) {
        int id = lane + t*32;
        v[t] = lg[id];
        if (v[t] > best) { best = v[t]; bi = id; }
    }
#pragma unroll
    for (int off = 16; off > 0; off >>= 1) {
        float ov = __shfl_down_sync(0xffffffffu, best, off);
        int   oi = __shfl_down_sync(0xffffffffu, bi,   off);
        if (ov > best || (ov == best && oi < bi)) { best = ov; bi = oi; }
    }
    best = __shfl_sync(0xffffffffu, best, 0);
    bi   = __shfl_sync(0xffffffffu, bi,   0);
    // second max (exclude bi) + keep-margin risk
    float second = -3.4e38f;
    bool riskm = false;
#pragma unroll
    for (int t = 0; t < 8; t++) {
        int id = lane + t*32;
        if (id != bi) {
            second = fmaxf(second, v[t]);
            if (fabsf(v[t] + 0.1f - best) < RISK_EPS) riskm = true;
        }
    }
#pragma unroll
    for (int off = 16; off > 0; off >>= 1)
        second = fmaxf(second, __shfl_down_sync(0xffffffffu, second, off));
    bool risk = __any_sync(0xffffffffu, riskm);
    if (lane == 0) {
        if ((best - second) < RISK_EPS || risk) {
            int slot = atomicAdd(&d_nrisk, 1);
            d_risk[slot] = row;
        }
    }
}

// ---------------- exact fp32 logits recompute for flagged rows ----------------
__global__ void __launch_bounds__(256) exact_rows_k(
    const float* __restrict__ x, const float* __restrict__ Wtr_b,
    const float* __restrict__ Wms_b)
{
    __shared__ float xs[DIN];   // 4 KB
    __shared__ float hs[HH];    // 8 KB
    int tid = threadIdx.x;
    int nr = d_nrisk;
    for (int it = blockIdx.x; it < nr; it += gridDim.x) {
        int row = d_risk[it];
        for (int i = tid; i < DIN; i += 256) xs[i] = x[(size_t)row*DIN + i];
        __syncthreads();
        for (int c = tid; c < HH; c += 256) {
            const float4* wp = (const float4*)(d_WtrT32 + (size_t)c*DIN);
            float s = 0.f;
#pragma unroll 4
            for (int k = 0; k < DIN/4; k++) {
                float4 wv = wp[k];
                const float* xp = xs + k*4;
                s += xp[0]*wv.x + xp[1]*wv.y + xp[2]*wv.z + xp[3]*wv.w;
            }
            hs[c] = fmaxf(s + Wtr_b[c], 0.f);
        }
        __syncthreads();
        for (int p = tid; p < KK; p += 256) {
            const float4* wp = (const float4*)(d_WmsT32 + (size_t)p*HH);
            float s = 0.f;
#pragma unroll 4
            for (int k = 0; k < HH/4; k++) {
                float4 wv = wp[k];
                const float* hp = hs + k*4;
                s += hp[0]*wv.x + hp[1]*wv.y + hp[2]*wv.z + hp[3]*wv.w;
            }
            d_logits[(size_t)row*KK + p] = s + Wms_b[p];
        }
        __syncthreads();
    }
}

// =======================================================================
// packed f32x2 GEMM (table GEMMs — known-correct)
// =======================================================================
__device__ __forceinline__ unsigned long long pack2f(float lo, float hi){
    unsigned long long r; asm("mov.b64 %0, {%1,%2};" : "=l"(r) : "f"(lo), "f"(hi)); return r;
}
__device__ __forceinline__ void unpack2f(unsigned long long v, float& lo, float& hi){
    asm("mov.b64 {%0,%1}, %2;" : "=f"(lo), "=f"(hi) : "l"(v));
}
__device__ __forceinline__ void ffma2(unsigned long long& d, unsigned long long a, unsigned long long b){
    asm("fma.rn.f32x2 %0, %1, %2, %0;" : "+l"(d) : "l"(a), "l"(b));
}

__global__ void __launch_bounds__(256, 2) gemm128(
    const float* __restrict__ A, const float* __restrict__ B,
    const float* __restrict__ bias, float* __restrict__ C,
    int M, int N, int Kd, float alpha, int doRelu)
{
    __shared__ float As[16][128];
    __shared__ float Bs[16][128];
    const int tid = threadIdx.x;
    const int bx = blockIdx.x, by = blockIdx.y;
    const int nz = gridDim.z;
    const int Kper = Kd / nz;
    const int kBase = blockIdx.z * Kper;
    const bool partial = (nz > 1);
    if (partial) C += (size_t)blockIdx.z * (size_t)M * N;

    const int aRow = tid >> 2;
    const int aCol = (tid & 3) << 2;
    const int bRow = tid >> 5;
    const int bCol = (tid & 31) << 2;
    const int tx = tid & 15, ty = tid >> 4;

    unsigned long long acc[4][8];
#pragma unroll
    for (int i = 0; i < 4; i++)
#pragma unroll
        for (int j = 0; j < 8; j++) acc[i][j] = 0ull;

    const float* Abase = A + (size_t)(by*128)*Kd + kBase;
    const float* Bbase = B + (size_t)kBase*N + bx*128;

    for (int k0 = 0; k0 < Kper; k0 += 16) {
#pragma unroll
        for (int i = 0; i < 2; i++) {
            int r = aRow + i*64;
            float4 v = *(const float4*)(Abase + (size_t)r*Kd + k0 + aCol);
            As[aCol+0][r] = v.x; As[aCol+1][r] = v.y;
            As[aCol+2][r] = v.z; As[aCol+3][r] = v.w;
        }
#pragma unroll
        for (int i = 0; i < 2; i++) {
            int r = bRow + i*8;
            *(float4*)&Bs[r][bCol] = *(const float4*)(Bbase + (size_t)(k0+r)*N + bCol);
        }
        __syncthreads();
#pragma unroll
        for (int kk = 0; kk < 16; kk++) {
            float4 av0 = *(const float4*)&As[kk][ty*8];
            float4 av1 = *(const float4*)&As[kk][ty*8+4];
            float4 bv0 = *(const float4*)&Bs[kk][tx*8];
            float4 bv1 = *(const float4*)&Bs[kk][tx*8+4];
            unsigned long long a2[4] = {
                pack2f(av0.x, av0.y), pack2f(av0.z, av0.w),
                pack2f(av1.x, av1.y), pack2f(av1.z, av1.w)};
            float bf[8] = {bv0.x,bv0.y,bv0.z,bv0.w,bv1.x,bv1.y,bv1.z,bv1.w};
#pragma unroll
            for (int j = 0; j < 8; j++) {
                unsigned long long bd = pack2f(bf[j], bf[j]);
#pragma unroll
                for (int i = 0; i < 4; i++) ffma2(acc[i][j], a2[i], bd);
            }
        }
        __syncthreads();
    }

    float out[8][8];
#pragma unroll
    for (int i2 = 0; i2 < 4; i2++)
#pragma unroll
        for (int j = 0; j < 8; j++)
            unpack2f(acc[i2][j], out[2*i2][j], out[2*i2+1][j]);

    float bl[8];
#pragma unroll
    for (int j = 0; j < 8; j++) bl[j] = 0.f;
    if (bias != nullptr && !partial) {
#pragma unroll
        for (int j = 0; j < 8; j++) bl[j] = bias[bx*128 + tx*8 + j];
    }

#pragma unroll
    for (int i = 0; i < 8; i++) {
        int row = by*128 + ty*8 + i;
        float* Crow = C + (size_t)row*N + bx*128 + tx*8;
        float vals[8];
#pragma unroll
        for (int j = 0; j < 8; j++) {
            float v = out[i][j];
            if (!partial) {
                v = v * alpha + bl[j];
                if (doRelu) v = fmaxf(v, 0.f);
            }
            vals[j] = v;
        }
        *(float4*)(Crow + 0) = make_float4(vals[0], vals[1], vals[2], vals[3]);
        *(float4*)(Crow + 4) = make_float4(vals[4], vals[5], vals[6], vals[7]);
    }
}

// ---------------- per-row argmax + keep-mask ----------------
__global__ void argmax_keep_k()
{
    int row = blockIdx.x * 8 + threadIdx.y;
    int lane = threadIdx.x;
    const float* lg = d_logits + (size_t)row * KK;
    float v[8];
    float best = -3.4e38f; int bi = 0;
#pragma unroll
    for (int t = 0; t < 8; t++) {
        int id = lane + t*32;
        v[t] = lg[id];
        if (v[t] > best) { best = v[t]; bi = id; }
    }
#pragma unroll
    for (int off = 16; off > 0; off >>= 1) {
        float ov = __shfl_down_sync(0xffffffffu, best, off);
        int   oi = __shfl_down_sync(0xffffffffu, bi,   off);
        if (ov > best || (ov == best && oi < bi)) { best = ov; bi = oi; }
    }
    best = __shfl_sync(0xffffffffu, best, 0);
    bi   = __shfl_sync(0xffffffffu, bi,   0);
    if (lane == 0) d_a0[row] = bi;
#pragma unroll
    for (int t = 0; t < 8; t++) {
        int id = lane + t*32;
        float adj = v[t] + 0.1f;
        bool k = (adj > best) || (adj == best && id < bi) || (id == bi);
        unsigned bw = __ballot_sync(0xffffffffu, k);
        if (lane == t) d_keep[(size_t)row*8 + t] = bw;
    }
}

// ---------------- segmented parallel mode scan ----------------
__global__ void seg_pre_k()
{
    __shared__ unsigned sm_m[SEGL*8];
    __shared__ int sm_a0[SEGL];
    __shared__ int sm_e[SEGL];
    int blk = blockIdx.x;
    int tid = threadIdx.x;
    size_t rbase = (size_t)blk * SEGL;
    for (int i = tid; i < SEGL*8; i += 256) sm_m[i] = d_keep[rbase*8 + i];
    for (int i = tid; i < SEGL; i += 256)   sm_a0[i] = d_a0[rbase + i];
    __syncthreads();
    if (tid < SEGL) {
        int v = sm_a0[tid];
        for (int s = tid + 1; s < SEGL; s++) {
            unsigned w = sm_m[s*8 + (v >> 5)];
            if (!((w >> (v & 31)) & 1u)) v = sm_a0[s];
        }
        sm_e[tid] = v;
    }
    __syncthreads();
    int p = tid;
    int ex = p;
    for (int s = 0; s < SEGL; s++) {
        unsigned w = sm_m[s*8 + (p >> 5)];
        if (!((w >> (p & 31)) & 1u)) { ex = sm_e[s]; break; }
    }
    d_exitv[blk * KK + p] = ex;
}

__global__ void chain_k(const float* __restrict__ prevm)
{
    int b = threadIdx.x;
    if (b < Bb) {
        int p = 0;
        for (int k = 0; k < KK; k++)
            if (prevm[b*KK + k] > 0.5f) { p = k; break; }
        for (int s = 0; s < NSEG; s++) {
            d_entry[b*NSEG + s] = p;
            p = d_exitv[(b*NSEG + s) * KK + p];
        }
    }
}

__global__ void seg_replay_k()
{
    __shared__ unsigned sm_m[SEGL*8];
    __shared__ int sm_a0[SEGL];
    __shared__ int sm_md[SEGL];
    int blk = blockIdx.x;
    int tid = threadIdx.x;
    size_t rbase = (size_t)blk * SEGL;
    for (int i = tid; i < SEGL*8; i += 256) sm_m[i] = d_keep[rbase*8 + i];
    for (int i = tid; i < SEGL; i += 256)   sm_a0[i] = d_a0[rbase + i];
    __syncthreads();
    if (tid == 0) {
        int p = d_entry[blk];
        for (int s = 0; s < SEGL; s++) {
            unsigned w = sm_m[s*8 + (p >> 5)];
            p = ((w >> (p & 31)) & 1u) ? p : sm_a0[s];
            sm_md[s] = p;
        }
    }
    __syncthreads();
    if (tid < SEGL) d_mode[rbase + tid] = sm_md[tid];
}

// ---------------- l2-normalize rows (optionally transposed output) ----------------
__global__ void l2norm_k(const float* __restrict__ in, float* __restrict__ out,
                         int nrows, int transpose)
{
    int row = blockIdx.x * 8 + threadIdx.y;
    if (row >= nrows) return;
    int lane = threadIdx.x;
    const float* p = in + (size_t)row * DM;
    float v[16]; float ss = 0.f;
#pragma unroll
    for (int t = 0; t < 16; t++) { v[t] = p[lane + t*32]; ss += v[t]*v[t]; }
#pragma unroll
    for (int off = 16; off > 0; off >>= 1) ss += __shfl_xor_sync(0xffffffffu, ss, off);
    float rn = 1.f / fmaxf(sqrtf(ss), 1e-12f);
    if (transpose) {
#pragma unroll
        for (int t = 0; t < 16; t++)
            out[(size_t)(lane + t*32) * BANKN + row] = v[t] * rn;
    } else {
#pragma unroll
        for (int t = 0; t < 16; t++)
            out[(size_t)row * DM + lane + t*32] = v[t] * rn;
    }
}

// ---------------- masked softmax over bank slots ----------------
__global__ void softmax_k(const float* __restrict__ used)
{
    int row = blockIdx.x;
    float* s = d_scores + (size_t)row * BANKN;
    int tid = threadIdx.x;  // 256
    __shared__ float red[256];
    float v[16];
    float mx = -3.4e38f;
#pragma unroll
    for (int t = 0; t < 16; t++) {
        int c = tid + t*256;
        float x = s[c];
        x = (used[c] > 0.5f) ? x : -1e30f;
        v[t] = x; mx = fmaxf(mx, x);
    }
    red[tid] = mx; __syncthreads();
    for (int o = 128; o > 0; o >>= 1) { if (tid < o) red[tid] = fmaxf(red[tid], red[tid+o]); __syncthreads(); }
    mx = red[0]; __syncthreads();
    float sum = 0.f;
#pragma unroll
    for (int t = 0; t < 16; t++) { v[t] = expf(v[t] - mx); sum += v[t]; }
    red[tid] = sum; __syncthreads();
    for (int o = 128; o > 0; o >>= 1) { if (tid < o) red[tid] += red[tid+o]; __syncthreads(); }
    float inv = 1.f / red[0];
#pragma unroll
    for (int t = 0; t < 16; t++) s[tid + t*256] = v[t] * inv;
}

// ---------------- reduce split-K partials ----------------
__global__ void reduce_bank_k()
{
    int i = blockIdx.x * 256 + threadIdx.x;
    float s = 0.f;
#pragma unroll
    for (int z = 0; z < 8; z++) s += d_part[(size_t)z*KK*DM + i];
    d_bankt[i] = s;
}

// ---------------- rms-norm with g ----------------
__global__ void rms_k(const float* __restrict__ Mw, const float* __restrict__ g)
{
    int k = blockIdx.x;
    int tid = threadIdx.x;  // 128
    __shared__ float red[128];
    float r[4]; float ss = 0.f;
#pragma unroll
    for (int t = 0; t < 4; t++) {
        int c = tid + t*128;
        r[t] = Mw[(size_t)k*DM + c] + d_bankt[(size_t)k*DM + c];
        ss += r[t]*r[t];
    }
    red[tid] = ss; __syncthreads();
    for (int o = 64; o > 0; o >>= 1) { if (tid < o) red[tid] += red[tid+o]; __syncthreads(); }
    float mean = red[0] / (float)DM;
    float sc = 1.f / sqrtf(mean + 1e-6f);
#pragma unroll
    for (int t = 0; t < 4; t++) {
        int c = tid + t*128;
        d_rn[(size_t)k*DM + c] = r[t] * g[c] * sc;
    }
}

// ---------------- gather y rows + scatter one-hot modes ----------------
__global__ void assemble_k(float* __restrict__ y, float* __restrict__ modes, int writeModes)
{
    int row = blockIdx.x;
    int t = threadIdx.x;  // 256
    int m = d_mode[row];
    float4 v = ((const float4*)(d_ytab + (size_t)m * DOUT))[t];
    ((float4*)(y + (size_t)row * DOUT))[t] = v;
    if (writeModes)
        modes[(size_t)row * KK + t] = (t == m) ? 1.f : 0.f;
}

// ---------------- launch ----------------
extern "C" void kernel_launch(void* const* d_in, const int* in_sizes, int n_in,
                              void* d_out, int out_size)
{
    const float* x     = (const float*)d_in[0];
    const float* prevm = (const float*)d_in[1];
    const float* Wtr_w = (const float*)d_in[2];
    const float* Wtr_b = (const float*)d_in[3];
    const float* Wms_w = (const float*)d_in[4];
    const float* Wms_b = (const float*)d_in[5];
    const float* Mw    = (const float*)d_in[6];
    const float* g     = (const float*)d_in[7];
    const float* Wrd_w = (const float*)d_in[8];
    const float* Wrd_b = (const float*)d_in[9];
    const float* bkeys = (const float*)d_in[10];
    const float* bvals = (const float*)d_in[11];
    const float* bused = (const float*)d_in[12];

    float* y = (float*)d_out;
    int writeModes = (out_size >= (int)((size_t)RR*DOUT + (size_t)RR*KK)) ? 1 : 0;
    float* modes = y + (size_t)RR * DOUT;

    void *pxhi, *pxlo, *phhi, *phlo, *pWthi, *pWtlo, *pWmhi, *pWmlo, *pWt32, *pWm32;
    void *plog, *pknT, *pqn, *pscores, *ppart, *prn, *pytab;
    cudaGetSymbolAddress(&pxhi, d_xhi);
    cudaGetSymbolAddress(&pxlo, d_xlo);
    cudaGetSymbolAddress(&phhi, d_hhi);
    cudaGetSymbolAddress(&phlo, d_hlo);
    cudaGetSymbolAddress(&pWthi, d_WtrThi);
    cudaGetSymbolAddress(&pWtlo, d_WtrTlo);
    cudaGetSymbolAddress(&pWmhi, d_WmsThi);
    cudaGetSymbolAddress(&pWmlo, d_WmsTlo);
    cudaGetSymbolAddress(&pWt32, d_WtrT32);
    cudaGetSymbolAddress(&pWm32, d_WmsT32);
    cudaGetSymbolAddress(&plog, d_logits);
    cudaGetSymbolAddress(&pknT, d_knT);
    cudaGetSymbolAddress(&pqn, d_qn);
    cudaGetSymbolAddress(&pscores, d_scores);
    cudaGetSymbolAddress(&ppart, d_part);
    cudaGetSymbolAddress(&prn, d_rn);
    cudaGetSymbolAddress(&pytab, d_ytab);

    cudaFuncSetAttribute(hgemm, cudaFuncAttributeMaxDynamicSharedMemorySize, HSMEM);

    // operand prep: split x, transpose+split weights (fp16 hi/lo + fp32 copy)
    split_k<<<(RR*DIN)/(256*4), 256>>>(x, (__half*)pxhi, (__half*)pxlo, RR*DIN);
    transpose_split_k<<<dim3(HH/32, DIN/32), dim3(32,8)>>>(Wtr_w, (__half*)pWthi, (__half*)pWtlo,
                                                           (float*)pWt32, DIN, HH);
    transpose_split_k<<<dim3(KK/32, HH/32), dim3(32,8)>>>(Wms_w, (__half*)pWmhi, (__half*)pWmlo,
                                                          (float*)pWm32, HH, KK);

    // GEMM1: h = relu(x @ Wtr + b) -> hi/lo fp16   [16384,2048]
    hgemm<<<dim3(HH/BN, RR/BM), 256, HSMEM>>>(
        (const __half*)pxhi, (const __half*)pxlo,
        (const __half*)pWthi, (const __half*)pWtlo,
        Wtr_b, nullptr, (__half*)phhi, (__half*)phlo, RR, HH, DIN, 1);

    // GEMM2: logits = h @ Wms + b -> fp32          [16384,256]
    hgemm<<<dim3(KK/BN, RR/BM), 256, HSMEM>>>(
        (const __half*)phhi, (const __half*)phlo,
        (const __half*)pWmhi, (const __half*)pWmlo,
        Wms_b, (float*)plog, nullptr, nullptr, RR, KK, HH, 0);

    // near-tie detection + exact fp32 recompute of risky rows
    zero_nrisk_k<<<1, 32>>>();
    flag_k<<<RR/8, dim3(32,8)>>>();
    exact_rows_k<<<256, 256>>>(x, Wtr_b, Wms_b);

    // per-row argmax + keep masks (reads fixed logits)
    argmax_keep_k<<<RR/8, dim3(32,8)>>>();
    // segmented parallel mode scan
    seg_pre_k<<<Bb*NSEG, 256>>>();
    chain_k<<<1, 32>>>(prevm);
    seg_replay_k<<<Bb*NSEG, 256>>>();

    // --- mode table construction (tiny; proven fp32 path) ---
    l2norm_k<<<BANKN/8, dim3(32,8)>>>(bkeys, (float*)pknT, BANKN, 1);
    l2norm_k<<<KK/8,    dim3(32,8)>>>(Mw,    (float*)pqn,  KK,    0);
    gemm128<<<dim3(BANKN/128, KK/128), 256>>>((const float*)pqn, (const float*)pknT, nullptr,
                                              (float*)pscores, KK, BANKN, DM, 4.0f, 0);
    softmax_k<<<KK, 256>>>(bused);
    gemm128<<<dim3(DM/128, KK/128, 8), 256>>>((const float*)pscores, bvals, nullptr,
                                              (float*)ppart, KK, DM, BANKN, 1.f, 0);
    reduce_bank_k<<<(KK*DM)/256, 256>>>();
    rms_k<<<KK, 128>>>(Mw, g);
    gemm128<<<dim3(DOUT/128, KK/128), 256>>>((const float*)prn, Wrd_w, Wrd_b,
                                             (float*)pytab, KK, DOUT, DM, 1.f, 0);

    // gather + one-hot scatter
    assemble_k<<<RR, 256>>>(y, modes, writeModes);
}

// round 15
// speedup vs baseline: 1.1874x; 1.1874x over previous
#include <cuda_runtime.h>
#include <cuda_fp16.h>
#include <cstdint>
#include <math.h>

// ---------------- problem dims ----------------
#define Bb   8
#define Ss   2048
#define RR   (Bb*Ss)       // 16384 rows
#define DIN  1024
#define HH   2048
#define KK   256
#define DM   512
#define DOUT 1024
#define BANKN 4096
#define SEGL 128
#define NSEG (Ss/SEGL)     // 16
#define RISK_EPS 3e-4f
#define MAXR 4096          // cap on exact-recompute rows

// ---------------- device scratch (static, allowed) ----------------
__device__ __half   d_xhi[(size_t)RR*DIN];
__device__ __half   d_xlo[(size_t)RR*DIN];
__device__ __half   d_hhi[(size_t)RR*HH];      // 67 MB
__device__ __half   d_hlo[(size_t)RR*HH];      // 67 MB
__device__ __half   d_WtrThi[(size_t)HH*DIN];
__device__ __half   d_WtrTlo[(size_t)HH*DIN];
__device__ __half   d_WmsThi[(size_t)KK*HH];
__device__ __half   d_WmsTlo[(size_t)KK*HH];
__device__ float    d_logits[(size_t)RR*KK];   // 16.8 MB
__device__ int      d_a0[RR];
__device__ unsigned d_keep[(size_t)RR*8];      // 256-bit keep masks
__device__ int      d_mode[RR];
__device__ int      d_exitv[Bb*NSEG*KK];
__device__ int      d_entry[Bb*NSEG];
__device__ int      d_risk[RR];
__device__ int      d_nrisk;
__device__ float    d_Xr[(size_t)MAXR*DIN];    // 16 MB compact flagged rows
__device__ float    d_Hr[(size_t)MAXR*HH];     // 32 MB
__device__ float    d_Lr[(size_t)MAXR*KK];     // 4 MB
__device__ float    d_knT[(size_t)DM*BANKN];   // normalized bank keys [DM,BANK]
__device__ float    d_qn[KK*DM];
__device__ float    d_scores[(size_t)KK*BANKN];
__device__ float    d_part[8*KK*DM];
__device__ float    d_bankt[KK*DM];
__device__ float    d_rn[KK*DM];
__device__ float    d_ytab[KK*DOUT];

// =======================================================================
// baseline-PTX helpers (all legal on compute_103)
// =======================================================================
__device__ __forceinline__ uint32_t smem_u32(const void* p){
    uint32_t a;
    asm("{ .reg .u64 t; cvta.to.shared.u64 t, %1; cvt.u32.u64 %0, t; }" : "=r"(a) : "l"(p));
    return a;
}
__device__ __forceinline__ void cpasync16(uint32_t dst, const void* src){
    asm volatile("cp.async.ca.shared.global [%0], [%1], 16;" :: "r"(dst), "l"(src));
}
#define CP_COMMIT() asm volatile("cp.async.commit_group;" ::: "memory")
#define CP_WAIT0()  asm volatile("cp.async.wait_group 0;" ::: "memory")

__device__ __forceinline__ void ldsm4(uint32_t* r, uint32_t addr){
    asm volatile("ldmatrix.sync.aligned.m8n8.x4.shared.b16 {%0,%1,%2,%3}, [%4];"
        : "=r"(r[0]), "=r"(r[1]), "=r"(r[2]), "=r"(r[3]) : "r"(addr));
}
__device__ __forceinline__ void mma16816(float* d, const uint32_t* a, const uint32_t* b){
    asm volatile("mma.sync.aligned.m16n8k16.row.col.f32.f16.f16.f32 "
        "{%0,%1,%2,%3}, {%4,%5,%6,%7}, {%8,%9}, {%0,%1,%2,%3};"
        : "+f"(d[0]), "+f"(d[1]), "+f"(d[2]), "+f"(d[3])
        : "r"(a[0]), "r"(a[1]), "r"(a[2]), "r"(a[3]), "r"(b[0]), "r"(b[1]));
}

// =======================================================================
// fp16-split (Markidis) tensor-core GEMM — unchanged from passing R14
// =======================================================================
#define BM 128
#define BN 128
#define BK 32
#define SSTR 40
#define TILEB (128*SSTR*2)
#define STAGEB (4*TILEB)
#define HSMEM (2*STAGEB)

__global__ void __launch_bounds__(256, 1) hgemm(
    const __half* __restrict__ Ahi, const __half* __restrict__ Alo,
    const __half* __restrict__ Bhi, const __half* __restrict__ Blo,
    const float* __restrict__ bias,
    float* __restrict__ Cf, __half* __restrict__ Chi, __half* __restrict__ Clo,
    int M, int Ntot, int K, int doRelu)
{
    extern __shared__ char sm[];
    const int tid  = threadIdx.x;
    const int lane = tid & 31;
    const int w    = tid >> 5;
    const int wm   = w & 3;
    const int wn   = w >> 2;
    const int bx = blockIdx.x, by = blockIdx.y;

    const uint32_t smb = smem_u32(sm);

    const __half* tb[4];
    tb[0] = Ahi + (size_t)(by*BM) * K;
    tb[1] = Alo + (size_t)(by*BM) * K;
    tb[2] = Bhi + (size_t)(bx*BN) * K;
    tb[3] = Blo + (size_t)(bx*BN) * K;

    float acc[2][8][4];
#pragma unroll
    for (int i = 0; i < 2; i++)
#pragma unroll
        for (int j = 0; j < 8; j++)
#pragma unroll
            for (int q = 0; q < 4; q++) acc[i][j][q] = 0.f;

    auto loadstage = [&](int st, int k0){
        uint32_t sb = smb + st * STAGEB;
#pragma unroll
        for (int m = 0; m < 4; m++) {
#pragma unroll
            for (int i = 0; i < 2; i++) {
                int idx = i*256 + tid;
                int row = idx >> 2, c4 = idx & 3;
                uint32_t dst = sb + m*TILEB + row*(SSTR*2) + c4*16;
                const __half* src = tb[m] + (size_t)row * K + k0 + c4*8;
                cpasync16(dst, src);
            }
        }
    };

    auto compute = [&](int st){
        uint32_t sA = smb + st * STAGEB;
        uint32_t sB = sA + 2*TILEB;
#pragma unroll
        for (int ks = 0; ks < 2; ks++) {
            uint32_t ahi[2][4], alo[2][4];
#pragma unroll
            for (int mt = 0; mt < 2; mt++) {
                int row  = wm*32 + mt*16 + (lane & 15);
                int koff = ks*16 + ((lane >> 4) << 3);
                uint32_t ad = sA + row*(SSTR*2) + koff*2;
                ldsm4(ahi[mt], ad);
                ldsm4(alo[mt], ad + TILEB);
            }
            uint32_t bhi[8][2], blo[8][2];
#pragma unroll
            for (int g = 0; g < 4; g++) {
                int nrow = wn*64 + g*16 + (lane & 7) + ((lane >> 4) << 3);
                int koff = ks*16 + (((lane >> 3) & 1) << 3);
                uint32_t bd = sB + nrow*(SSTR*2) + koff*2;
                uint32_t t4[4];
                ldsm4(t4, bd);
                bhi[2*g][0] = t4[0]; bhi[2*g][1] = t4[1];
                bhi[2*g+1][0] = t4[2]; bhi[2*g+1][1] = t4[3];
                ldsm4(t4, bd + TILEB);
                blo[2*g][0] = t4[0]; blo[2*g][1] = t4[1];
                blo[2*g+1][0] = t4[2]; blo[2*g+1][1] = t4[3];
            }
#pragma unroll
            for (int mt = 0; mt < 2; mt++)
#pragma unroll
                for (int nt = 0; nt < 8; nt++) {
                    mma16816(acc[mt][nt], ahi[mt], bhi[nt]);
                    mma16816(acc[mt][nt], ahi[mt], blo[nt]);
                    mma16816(acc[mt][nt], alo[mt], bhi[nt]);
                }
        }
    };

    const int NC = K / BK;
    loadstage(0, 0); CP_COMMIT();
    CP_WAIT0(); __syncthreads();
    for (int c = 0; c < NC; c++) {
        int cur = c & 1;
        if (c + 1 < NC) { loadstage(cur ^ 1, (c + 1) * BK); CP_COMMIT(); }
        compute(cur);
        if (c + 1 < NC) { CP_WAIT0(); __syncthreads(); }
    }

#pragma unroll
    for (int mt = 0; mt < 2; mt++) {
#pragma unroll
        for (int nt = 0; nt < 8; nt++) {
            int r0 = by*BM + wm*32 + mt*16 + (lane >> 2);
            int c0 = bx*BN + wn*64 + nt*8 + (lane & 3)*2;
            float b0 = bias ? bias[c0]   : 0.f;
            float b1 = bias ? bias[c0+1] : 0.f;
            float v0 = acc[mt][nt][0] + b0;
            float v1 = acc[mt][nt][1] + b1;
            float v2 = acc[mt][nt][2] + b0;
            float v3 = acc[mt][nt][3] + b1;
            if (doRelu) {
                v0 = fmaxf(v0, 0.f); v1 = fmaxf(v1, 0.f);
                v2 = fmaxf(v2, 0.f); v3 = fmaxf(v3, 0.f);
            }
            if (Cf) {
                *(float2*)(Cf + (size_t)r0 * Ntot + c0)       = make_float2(v0, v1);
                *(float2*)(Cf + (size_t)(r0+8) * Ntot + c0)   = make_float2(v2, v3);
            } else {
                __half h0 = __float2half_rn(v0), h1 = __float2half_rn(v1);
                __half h2 = __float2half_rn(v2), h3 = __float2half_rn(v3);
                __half l0 = __float2half_rn(v0 - __half2float(h0));
                __half l1 = __float2half_rn(v1 - __half2float(h1));
                __half l2 = __float2half_rn(v2 - __half2float(h2));
                __half l3 = __float2half_rn(v3 - __half2float(h3));
                *(__half2*)(Chi + (size_t)r0 * Ntot + c0)     = __halves2half2(h0, h1);
                *(__half2*)(Chi + (size_t)(r0+8) * Ntot + c0) = __halves2half2(h2, h3);
                *(__half2*)(Clo + (size_t)r0 * Ntot + c0)     = __halves2half2(l0, l1);
                *(__half2*)(Clo + (size_t)(r0+8) * Ntot + c0) = __halves2half2(l2, l3);
            }
        }
    }
}

// ---------------- fp32 -> fp16 hi/lo split ----------------
__global__ void split_k(const float* __restrict__ in, __half* __restrict__ hi,
                        __half* __restrict__ lo, int n)
{
    int i = (blockIdx.x * 256 + threadIdx.x) * 4;
    if (i >= n) return;
    float4 v = *(const float4*)(in + i);
    __half h0 = __float2half_rn(v.x), h1 = __float2half_rn(v.y);
    __half h2 = __float2half_rn(v.z), h3 = __float2half_rn(v.w);
    *(__half2*)(hi + i)     = __halves2half2(h0, h1);
    *(__half2*)(hi + i + 2) = __halves2half2(h2, h3);
    __half l0 = __float2half_rn(v.x - __half2float(h0));
    __half l1 = __float2half_rn(v.y - __half2float(h1));
    __half l2 = __float2half_rn(v.z - __half2float(h2));
    __half l3 = __float2half_rn(v.w - __half2float(h3));
    *(__half2*)(lo + i)     = __halves2half2(l0, l1);
    *(__half2*)(lo + i + 2) = __halves2half2(l2, l3);
}

// ---------------- transpose [R,C] fp32 -> [C,R] fp16 hi/lo ----------------
__global__ void transpose_split_k(const float* __restrict__ in,
                                  __half* __restrict__ hi, __half* __restrict__ lo,
                                  int R, int C)
{
    __shared__ float t[32][33];
    int c0 = blockIdx.x * 32, r0 = blockIdx.y * 32;
    int x = threadIdx.x, y = threadIdx.y;
    for (int i = y; i < 32; i += 8) t[i][x] = in[(size_t)(r0 + i) * C + c0 + x];
    __syncthreads();
    for (int i = y; i < 32; i += 8) {
        float v = t[x][i];
        __half h = __float2half_rn(v);
        __half l = __float2half_rn(v - __half2float(h));
        size_t o = (size_t)(c0 + i) * R + r0 + x;
        hi[o] = h; lo[o] = l;
    }
}

// ---------------- risk counter reset ----------------
__global__ void zero_nrisk_k() { if (threadIdx.x == 0) d_nrisk = 0; }

// ---------------- flag rows with near-tie decisions ----------------
__global__ void flag_k()
{
    int row = blockIdx.x * 8 + threadIdx.y;
    int lane = threadIdx.x;
    const float* lg = d_logits + (size_t)row * KK;
    float v[8];
    float best = -3.4e38f; int bi = 0;
#pragma unroll
    for (int t = 0; t < 8; t++) {
        int id = lane + t*32;
        v[t] = lg[id];
        if (v[t] > best) { best = v[t]; bi = id; }
    }
#pragma unroll
    for (int off = 16; off > 0; off >>= 1) {
        float ov = __shfl_down_sync(0xffffffffu, best, off);
        int   oi = __shfl_down_sync(0xffffffffu, bi,   off);
        if (ov > best || (ov == best && oi < bi)) { best = ov; bi = oi; }
    }
    best = __shfl_sync(0xffffffffu, best, 0);
    bi   = __shfl_sync(0xffffffffu, bi,   0);
    float second = -3.4e38f;
    bool riskm = false;
#pragma unroll
    for (int t = 0; t < 8; t++) {
        int id = lane + t*32;
        if (id != bi) {
            second = fmaxf(second, v[t]);
            if (fabsf(v[t] + 0.1f - best) < RISK_EPS) riskm = true;
        }
    }
#pragma unroll
    for (int off = 16; off > 0; off >>= 1)
        second = fmaxf(second, __shfl_down_sync(0xffffffffu, second, off));
    bool risk = __any_sync(0xffffffffu, riskm);
    if (lane == 0) {
        if ((best - second) < RISK_EPS || risk) {
            int slot = atomicAdd(&d_nrisk, 1);
            if (slot < MAXR) d_risk[slot] = row;
        }
    }
}

// ---------------- gather flagged x rows into compact Xr (zero-padded) ----------------
__global__ void gather_x_k(const float* __restrict__ x)
{
    int nr = d_nrisk; if (nr > MAXR) nr = MAXR;
    int nrp = (nr + 127) & ~127;
    int r = blockIdx.x;
    if (r >= nrp) return;
    float4 v = make_float4(0.f, 0.f, 0.f, 0.f);
    if (r < nr) {
        int src = d_risk[r];
        v = ((const float4*)(x + (size_t)src * DIN))[threadIdx.x];
    }
    ((float4*)(d_Xr + (size_t)r * DIN))[threadIdx.x] = v;
}

// ---------------- scatter exact logits back ----------------
__global__ void scatter_logits_k()
{
    int nr = d_nrisk; if (nr > MAXR) nr = MAXR;
    int r = blockIdx.x;
    if (r >= nr) return;
    int dst = d_risk[r];
    d_logits[(size_t)dst * KK + threadIdx.x] = d_Lr[(size_t)r * KK + threadIdx.x];
}

// =======================================================================
// packed f32x2 GEMM (table GEMMs — known-correct) + dynamic-M variant
// =======================================================================
__device__ __forceinline__ unsigned long long pack2f(float lo, float hi){
    unsigned long long r; asm("mov.b64 %0, {%1,%2};" : "=l"(r) : "f"(lo), "f"(hi)); return r;
}
__device__ __forceinline__ void unpack2f(unsigned long long v, float& lo, float& hi){
    asm("mov.b64 {%0,%1}, %2;" : "=f"(lo), "=f"(hi) : "l"(v));
}
__device__ __forceinline__ void ffma2(unsigned long long& d, unsigned long long a, unsigned long long b){
    asm("fma.rn.f32x2 %0, %1, %2, %0;" : "+l"(d) : "l"(a), "l"(b));
}

// core body shared by both variants
__device__ __forceinline__ void gemm128_body(
    const float* __restrict__ A, const float* __restrict__ B,
    const float* __restrict__ bias, float* __restrict__ C,
    int M, int N, int Kd, float alpha, int doRelu,
    int bx, int by, int nz, int bz)
{
    __shared__ float As[16][128];
    __shared__ float Bs[16][128];
    const int tid = threadIdx.x;
    const int Kper = Kd / nz;
    const int kBase = bz * Kper;
    const bool partial = (nz > 1);
    if (partial) C += (size_t)bz * (size_t)M * N;

    const int aRow = tid >> 2;
    const int aCol = (tid & 3) << 2;
    const int bRow = tid >> 5;
    const int bCol = (tid & 31) << 2;
    const int tx = tid & 15, ty = tid >> 4;

    unsigned long long acc[4][8];
#pragma unroll
    for (int i = 0; i < 4; i++)
#pragma unroll
        for (int j = 0; j < 8; j++) acc[i][j] = 0ull;

    const float* Abase = A + (size_t)(by*128)*Kd + kBase;
    const float* Bbase = B + (size_t)kBase*N + bx*128;

    for (int k0 = 0; k0 < Kper; k0 += 16) {
#pragma unroll
        for (int i = 0; i < 2; i++) {
            int r = aRow + i*64;
            float4 v = *(const float4*)(Abase + (size_t)r*Kd + k0 + aCol);
            As[aCol+0][r] = v.x; As[aCol+1][r] = v.y;
            As[aCol+2][r] = v.z; As[aCol+3][r] = v.w;
        }
#pragma unroll
        for (int i = 0; i < 2; i++) {
            int r = bRow + i*8;
            *(float4*)&Bs[r][bCol] = *(const float4*)(Bbase + (size_t)(k0+r)*N + bCol);
        }
        __syncthreads();
#pragma unroll
        for (int kk = 0; kk < 16; kk++) {
            float4 av0 = *(const float4*)&As[kk][ty*8];
            float4 av1 = *(const float4*)&As[kk][ty*8+4];
            float4 bv0 = *(const float4*)&Bs[kk][tx*8];
            float4 bv1 = *(const float4*)&Bs[kk][tx*8+4];
            unsigned long long a2[4] = {
                pack2f(av0.x, av0.y), pack2f(av0.z, av0.w),
                pack2f(av1.x, av1.y), pack2f(av1.z, av1.w)};
            float bf[8] = {bv0.x,bv0.y,bv0.z,bv0.w,bv1.x,bv1.y,bv1.z,bv1.w};
#pragma unroll
            for (int j = 0; j < 8; j++) {
                unsigned long long bd = pack2f(bf[j], bf[j]);
#pragma unroll
                for (int i = 0; i < 4; i++) ffma2(acc[i][j], a2[i], bd);
            }
        }
        __syncthreads();
    }

    float out[8][8];
#pragma unroll
    for (int i2 = 0; i2 < 4; i2++)
#pragma unroll
        for (int j = 0; j < 8; j++)
            unpack2f(acc[i2][j], out[2*i2][j], out[2*i2+1][j]);

    float bl[8];
#pragma unroll
    for (int j = 0; j < 8; j++) bl[j] = 0.f;
    if (bias != nullptr && !partial) {
#pragma unroll
        for (int j = 0; j < 8; j++) bl[j] = bias[bx*128 + tx*8 + j];
    }

#pragma unroll
    for (int i = 0; i < 8; i++) {
        int row = by*128 + ty*8 + i;
        float* Crow = C + (size_t)row*N + bx*128 + tx*8;
        float vals[8];
#pragma unroll
        for (int j = 0; j < 8; j++) {
            float v = out[i][j];
            if (!partial) {
                v = v * alpha + bl[j];
                if (doRelu) v = fmaxf(v, 0.f);
            }
            vals[j] = v;
        }
        *(float4*)(Crow + 0) = make_float4(vals[0], vals[1], vals[2], vals[3]);
        *(float4*)(Crow + 4) = make_float4(vals[4], vals[5], vals[6], vals[7]);
    }
}

__global__ void __launch_bounds__(256, 2) gemm128(
    const float* __restrict__ A, const float* __restrict__ B,
    const float* __restrict__ bias, float* __restrict__ C,
    int M, int N, int Kd, float alpha, int doRelu)
{
    gemm128_body(A, B, bias, C, M, N, Kd, alpha, doRelu,
                 blockIdx.x, blockIdx.y, gridDim.z, blockIdx.z);
}

// dynamic-M: row-tile count derived from d_nrisk; unused tiles exit
__global__ void __launch_bounds__(256, 2) gemm128_dyn(
    const float* __restrict__ A, const float* __restrict__ B,
    const float* __restrict__ bias, float* __restrict__ C,
    int N, int Kd, int doRelu)
{
    int nr = d_nrisk; if (nr > MAXR) nr = MAXR;
    int nrp = (nr + 127) & ~127;
    if (blockIdx.y * 128 >= nrp) return;
    gemm128_body(A, B, bias, C, nrp, N, Kd, 1.f, doRelu,
                 blockIdx.x, blockIdx.y, 1, 0);
}

// ---------------- per-row argmax + keep-mask ----------------
__global__ void argmax_keep_k()
{
    int row = blockIdx.x * 8 + threadIdx.y;
    int lane = threadIdx.x;
    const float* lg = d_logits + (size_t)row * KK;
    float v[8];
    float best = -3.4e38f; int bi = 0;
#pragma unroll
    for (int t = 0; t < 8; t++) {
        int id = lane + t*32;
        v[t] = lg[id];
        if (v[t] > best) { best = v[t]; bi = id; }
    }
#pragma unroll
    for (int off = 16; off > 0; off >>= 1) {
        float ov = __shfl_down_sync(0xffffffffu, best, off);
        int   oi = __shfl_down_sync(0xffffffffu, bi,   off);
        if (ov > best || (ov == best && oi < bi)) { best = ov; bi = oi; }
    }
    best = __shfl_sync(0xffffffffu, best, 0);
    bi   = __shfl_sync(0xffffffffu, bi,   0);
    if (lane == 0) d_a0[row] = bi;
#pragma unroll
    for (int t = 0; t < 8; t++) {
        int id = lane + t*32;
        float adj = v[t] + 0.1f;
        bool k = (adj > best) || (adj == best && id < bi) || (id == bi);
        unsigned bw = __ballot_sync(0xffffffffu, k);
        if (lane == t) d_keep[(size_t)row*8 + t] = bw;
    }
}

// ---------------- segmented parallel mode scan ----------------
__global__ void seg_pre_k()
{
    __shared__ unsigned sm_m[SEGL*8];
    __shared__ int sm_a0[SEGL];
    __shared__ int sm_e[SEGL];
    int blk = blockIdx.x;
    int tid = threadIdx.x;
    size_t rbase = (size_t)blk * SEGL;
    for (int i = tid; i < SEGL*8; i += 256) sm_m[i] = d_keep[rbase*8 + i];
    for (int i = tid; i < SEGL; i += 256)   sm_a0[i] = d_a0[rbase + i];
    __syncthreads();
    if (tid < SEGL) {
        int v = sm_a0[tid];
        for (int s = tid + 1; s < SEGL; s++) {
            unsigned w = sm_m[s*8 + (v >> 5)];
            if (!((w >> (v & 31)) & 1u)) v = sm_a0[s];
        }
        sm_e[tid] = v;
    }
    __syncthreads();
    int p = tid;
    int ex = p;
    for (int s = 0; s < SEGL; s++) {
        unsigned w = sm_m[s*8 + (p >> 5)];
        if (!((w >> (p & 31)) & 1u)) { ex = sm_e[s]; break; }
    }
    d_exitv[blk * KK + p] = ex;
}

__global__ void chain_k(const float* __restrict__ prevm)
{
    int b = threadIdx.x;
    if (b < Bb) {
        int p = 0;
        for (int k = 0; k < KK; k++)
            if (prevm[b*KK + k] > 0.5f) { p = k; break; }
        for (int s = 0; s < NSEG; s++) {
            d_entry[b*NSEG + s] = p;
            p = d_exitv[(b*NSEG + s) * KK + p];
        }
    }
}

__global__ void seg_replay_k()
{
    __shared__ unsigned sm_m[SEGL*8];
    __shared__ int sm_a0[SEGL];
    __shared__ int sm_md[SEGL];
    int blk = blockIdx.x;
    int tid = threadIdx.x;
    size_t rbase = (size_t)blk * SEGL;
    for (int i = tid; i < SEGL*8; i += 256) sm_m[i] = d_keep[rbase*8 + i];
    for (int i = tid; i < SEGL; i += 256)   sm_a0[i] = d_a0[rbase + i];
    __syncthreads();
    if (tid == 0) {
        int p = d_entry[blk];
        for (int s = 0; s < SEGL; s++) {
            unsigned w = sm_m[s*8 + (p >> 5)];
            p = ((w >> (p & 31)) & 1u) ? p : sm_a0[s];
            sm_md[s] = p;
        }
    }
    __syncthreads();
    if (tid < SEGL) d_mode[rbase + tid] = sm_md[tid];
}

// ---------------- l2-normalize rows (optionally transposed output) ----------------
__global__ void l2norm_k(const float* __restrict__ in, float* __restrict__ out,
                         int nrows, int transpose)
{
    int row = blockIdx.x * 8 + threadIdx.y;
    if (row >= nrows) return;
    int lane = threadIdx.x;
    const float* p = in + (size_t)row * DM;
    float v[16]; float ss = 0.f;
#pragma unroll
    for (int t = 0; t < 16; t++) { v[t] = p[lane + t*32]; ss += v[t]*v[t]; }
#pragma unroll
    for (int off = 16; off > 0; off >>= 1) ss += __shfl_xor_sync(0xffffffffu, ss, off);
    float rn = 1.f / fmaxf(sqrtf(ss), 1e-12f);
    if (transpose) {
#pragma unroll
        for (int t = 0; t < 16; t++)
            out[(size_t)(lane + t*32) * BANKN + row] = v[t] * rn;
    } else {
#pragma unroll
        for (int t = 0; t < 16; t++)
            out[(size_t)row * DM + lane + t*32] = v[t] * rn;
    }
}

// ---------------- masked softmax over bank slots ----------------
__global__ void softmax_k(const float* __restrict__ used)
{
    int row = blockIdx.x;
    float* s = d_scores + (size_t)row * BANKN;
    int tid = threadIdx.x;  // 256
    __shared__ float red[256];
    float v[16];
    float mx = -3.4e38f;
#pragma unroll
    for (int t = 0; t < 16; t++) {
        int c = tid + t*256;
        float x = s[c];
        x = (used[c] > 0.5f) ? x : -1e30f;
        v[t] = x; mx = fmaxf(mx, x);
    }
    red[tid] = mx; __syncthreads();
    for (int o = 128; o > 0; o >>= 1) { if (tid < o) red[tid] = fmaxf(red[tid], red[tid+o]); __syncthreads(); }
    mx = red[0]; __syncthreads();
    float sum = 0.f;
#pragma unroll
    for (int t = 0; t < 16; t++) { v[t] = expf(v[t] - mx); sum += v[t]; }
    red[tid] = sum; __syncthreads();
    for (int o = 128; o > 0; o >>= 1) { if (tid < o) red[tid] += red[tid+o]; __syncthreads(); }
    float inv = 1.f / red[0];
#pragma unroll
    for (int t = 0; t < 16; t++) s[tid + t*256] = v[t] * inv;
}

// ---------------- reduce split-K partials ----------------
__global__ void reduce_bank_k()
{
    int i = blockIdx.x * 256 + threadIdx.x;
    float s = 0.f;
#pragma unroll
    for (int z = 0; z < 8; z++) s += d_part[(size_t)z*KK*DM + i];
    d_bankt[i] = s;
}

// ---------------- rms-norm with g ----------------
__global__ void rms_k(const float* __restrict__ Mw, const float* __restrict__ g)
{
    int k = blockIdx.x;
    int tid = threadIdx.x;  // 128
    __shared__ float red[128];
    float r[4]; float ss = 0.f;
#pragma unroll
    for (int t = 0; t < 4; t++) {
        int c = tid + t*128;
        r[t] = Mw[(size_t)k*DM + c] + d_bankt[(size_t)k*DM + c];
        ss += r[t]*r[t];
    }
    red[tid] = ss; __syncthreads();
    for (int o = 64; o > 0; o >>= 1) { if (tid < o) red[tid] += red[tid+o]; __syncthreads(); }
    float mean = red[0] / (float)DM;
    float sc = 1.f / sqrtf(mean + 1e-6f);
#pragma unroll
    for (int t = 0; t < 4; t++) {
        int c = tid + t*128;
        d_rn[(size_t)k*DM + c] = r[t] * g[c] * sc;
    }
}

// ---------------- gather y rows + scatter one-hot modes ----------------
__global__ void assemble_k(float* __restrict__ y, float* __restrict__ modes, int writeModes)
{
    int row = blockIdx.x;
    int t = threadIdx.x;  // 256
    int m = d_mode[row];
    float4 v = ((const float4*)(d_ytab + (size_t)m * DOUT))[t];
    ((float4*)(y + (size_t)row * DOUT))[t] = v;
    if (writeModes)
        modes[(size_t)row * KK + t] = (t == m) ? 1.f : 0.f;
}

// ---------------- launch ----------------
extern "C" void kernel_launch(void* const* d_in, const int* in_sizes, int n_in,
                              void* d_out, int out_size)
{
    const float* x     = (const float*)d_in[0];
    const float* prevm = (const float*)d_in[1];
    const float* Wtr_w = (const float*)d_in[2];
    const float* Wtr_b = (const float*)d_in[3];
    const float* Wms_w = (const float*)d_in[4];
    const float* Wms_b = (const float*)d_in[5];
    const float* Mw    = (const float*)d_in[6];
    const float* g     = (const float*)d_in[7];
    const float* Wrd_w = (const float*)d_in[8];
    const float* Wrd_b = (const float*)d_in[9];
    const float* bkeys = (const float*)d_in[10];
    const float* bvals = (const float*)d_in[11];
    const float* bused = (const float*)d_in[12];

    float* y = (float*)d_out;
    int writeModes = (out_size >= (int)((size_t)RR*DOUT + (size_t)RR*KK)) ? 1 : 0;
    float* modes = y + (size_t)RR * DOUT;

    void *pxhi, *pxlo, *phhi, *phlo, *pWthi, *pWtlo, *pWmhi, *pWmlo;
    void *plog, *pknT, *pqn, *pscores, *ppart, *prn, *pytab, *pXr, *pHr, *pLr;
    cudaGetSymbolAddress(&pxhi, d_xhi);
    cudaGetSymbolAddress(&pxlo, d_xlo);
    cudaGetSymbolAddress(&phhi, d_hhi);
    cudaGetSymbolAddress(&phlo, d_hlo);
    cudaGetSymbolAddress(&pWthi, d_WtrThi);
    cudaGetSymbolAddress(&pWtlo, d_WtrTlo);
    cudaGetSymbolAddress(&pWmhi, d_WmsThi);
    cudaGetSymbolAddress(&pWmlo, d_WmsTlo);
    cudaGetSymbolAddress(&plog, d_logits);
    cudaGetSymbolAddress(&pknT, d_knT);
    cudaGetSymbolAddress(&pqn, d_qn);
    cudaGetSymbolAddress(&pscores, d_scores);
    cudaGetSymbolAddress(&ppart, d_part);
    cudaGetSymbolAddress(&prn, d_rn);
    cudaGetSymbolAddress(&pytab, d_ytab);
    cudaGetSymbolAddress(&pXr, d_Xr);
    cudaGetSymbolAddress(&pHr, d_Hr);
    cudaGetSymbolAddress(&pLr, d_Lr);

    cudaFuncSetAttribute(hgemm, cudaFuncAttributeMaxDynamicSharedMemorySize, HSMEM);

    // operand prep: split x, transpose+split weights
    split_k<<<(RR*DIN)/(256*4), 256>>>(x, (__half*)pxhi, (__half*)pxlo, RR*DIN);
    transpose_split_k<<<dim3(HH/32, DIN/32), dim3(32,8)>>>(Wtr_w, (__half*)pWthi, (__half*)pWtlo, DIN, HH);
    transpose_split_k<<<dim3(KK/32, HH/32), dim3(32,8)>>>(Wms_w, (__half*)pWmhi, (__half*)pWmlo, HH, KK);

    // GEMM1: h = relu(x @ Wtr + b) -> hi/lo fp16   [16384,2048]
    hgemm<<<dim3(HH/BN, RR/BM), 256, HSMEM>>>(
        (const __half*)pxhi, (const __half*)pxlo,
        (const __half*)pWthi, (const __half*)pWtlo,
        Wtr_b, nullptr, (__half*)phhi, (__half*)phlo, RR, HH, DIN, 1);

    // GEMM2: logits = h @ Wms + b -> fp32          [16384,256]
    hgemm<<<dim3(KK/BN, RR/BM), 256, HSMEM>>>(
        (const __half*)phhi, (const __half*)phlo,
        (const __half*)pWmhi, (const __half*)pWmlo,
        Wms_b, (float*)plog, nullptr, nullptr, RR, KK, HH, 0);

    // near-tie detection + weight-stationary exact fp32 recompute
    zero_nrisk_k<<<1, 32>>>();
    flag_k<<<RR/8, dim3(32,8)>>>();
    gather_x_k<<<MAXR, 256>>>(x);
    // Hr = relu(Xr @ Wtr + b) : B = Wtr_w [DIN,HH] row-major (K-major for gemm128)
    gemm128_dyn<<<dim3(HH/128, MAXR/128), 256>>>((const float*)pXr, Wtr_w, Wtr_b,
                                                 (float*)pHr, HH, DIN, 1);
    // Lr = Hr @ Wms + b
    gemm128_dyn<<<dim3(KK/128, MAXR/128), 256>>>((const float*)pHr, Wms_w, Wms_b,
                                                 (float*)pLr, KK, HH, 0);
    scatter_logits_k<<<MAXR, 256>>>();

    // per-row argmax + keep masks (reads fixed logits)
    argmax_keep_k<<<RR/8, dim3(32,8)>>>();
    // segmented parallel mode scan
    seg_pre_k<<<Bb*NSEG, 256>>>();
    chain_k<<<1, 32>>>(prevm);
    seg_replay_k<<<Bb*NSEG, 256>>>();

    // --- mode table construction (tiny; proven fp32 path) ---
    l2norm_k<<<BANKN/8, dim3(32,8)>>>(bkeys, (float*)pknT, BANKN, 1);
    l2norm_k<<<KK/8,    dim3(32,8)>>>(Mw,    (float*)pqn,  KK,    0);
    gemm128<<<dim3(BANKN/128, KK/128), 256>>>((const float*)pqn, (const float*)pknT, nullptr,
                                              (float*)pscores, KK, BANKN, DM, 4.0f, 0);
    softmax_k<<<KK, 256>>>(bused);
    gemm128<<<dim3(DM/128, KK/128, 8), 256>>>((const float*)pscores, bvals, nullptr,
                                              (float*)ppart, KK, DM, BANKN, 1.f, 0);
    reduce_bank_k<<<(KK*DM)/256, 256>>>();
    rms_k<<<KK, 128>>>(Mw, g);
    gemm128<<<dim3(DOUT/128, KK/128), 256>>>((const float*)prn, Wrd_w, Wrd_b,
                                             (float*)pytab, KK, DOUT, DM, 1.f, 0);

    // gather + one-hot scatter
    assemble_k<<<RR, 256>>>(y, modes, writeModes);
}

// round 16
// speedup vs baseline: 1.1913x; 1.0033x over previous
#include <cuda_runtime.h>
#include <cuda_fp16.h>
#include <cstdint>
#include <math.h>

// ---------------- problem dims ----------------
#define Bb   8
#define Ss   2048
#define RR   (Bb*Ss)       // 16384 rows
#define DIN  1024
#define HH   2048
#define KK   256
#define DM   512
#define DOUT 1024
#define BANKN 4096
#define SEGL 128
#define NSEG (Ss/SEGL)     // 16
#define RISK_EPS 3e-4f
#define MAXR 4096          // cap on exact-recompute rows

// ---------------- device scratch (static, allowed) ----------------
__device__ __half   d_xhi[(size_t)RR*DIN];
__device__ __half   d_xlo[(size_t)RR*DIN];
__device__ __half   d_hhi[(size_t)RR*HH];      // 67 MB
__device__ __half   d_hlo[(size_t)RR*HH];      // 67 MB
__device__ __half   d_WtrThi[(size_t)HH*DIN];
__device__ __half   d_WtrTlo[(size_t)HH*DIN];
__device__ __half   d_WmsThi[(size_t)KK*HH];
__device__ __half   d_WmsTlo[(size_t)KK*HH];
__device__ float    d_logits[(size_t)RR*KK];   // 16.8 MB
__device__ int      d_a0[RR];
__device__ unsigned d_keep[(size_t)RR*8];      // 256-bit keep masks
__device__ int      d_mode[RR];
__device__ int      d_exitv[Bb*NSEG*KK];
__device__ int      d_entry[Bb*NSEG];
__device__ int      d_risk[RR];
__device__ int      d_nrisk;
__device__ float    d_Xr[(size_t)MAXR*DIN];    // 16 MB compact flagged rows
__device__ float    d_Hr[(size_t)MAXR*HH];     // 32 MB
__device__ float    d_Lr[(size_t)MAXR*KK];     // 4 MB
__device__ float    d_knT[(size_t)DM*BANKN];   // normalized bank keys [DM,BANK]
__device__ float    d_qn[KK*DM];
__device__ float    d_scores[(size_t)KK*BANKN];
__device__ float    d_part[8*KK*DM];
__device__ float    d_bankt[KK*DM];
__device__ float    d_rn[KK*DM];
__device__ float    d_ytab[KK*DOUT];

// =======================================================================
// baseline-PTX helpers (all legal on compute_103)
// =======================================================================
__device__ __forceinline__ uint32_t smem_u32(const void* p){
    uint32_t a;
    asm("{ .reg .u64 t; cvta.to.shared.u64 t, %1; cvt.u32.u64 %0, t; }" : "=r"(a) : "l"(p));
    return a;
}
__device__ __forceinline__ void cpasync16(uint32_t dst, const void* src){
    asm volatile("cp.async.ca.shared.global [%0], [%1], 16;" :: "r"(dst), "l"(src));
}
#define CP_COMMIT() asm volatile("cp.async.commit_group;" ::: "memory")
#define CP_WAIT0()  asm volatile("cp.async.wait_group 0;" ::: "memory")

__device__ __forceinline__ void ldsm4(uint32_t* r, uint32_t addr){
    asm volatile("ldmatrix.sync.aligned.m8n8.x4.shared.b16 {%0,%1,%2,%3}, [%4];"
        : "=r"(r[0]), "=r"(r[1]), "=r"(r[2]), "=r"(r[3]) : "r"(addr));
}
__device__ __forceinline__ void mma16816(float* d, const uint32_t* a, const uint32_t* b){
    asm volatile("mma.sync.aligned.m16n8k16.row.col.f32.f16.f16.f32 "
        "{%0,%1,%2,%3}, {%4,%5,%6,%7}, {%8,%9}, {%0,%1,%2,%3};"
        : "+f"(d[0]), "+f"(d[1]), "+f"(d[2]), "+f"(d[3])
        : "r"(a[0]), "r"(a[1]), "r"(a[2]), "r"(a[3]), "r"(b[0]), "r"(b[1]));
}

// =======================================================================
// fp16-split (Markidis) tensor-core GEMM — unchanged from passing R14
// =======================================================================
#define BM 128
#define BN 128
#define BK 32
#define SSTR 40
#define TILEB (128*SSTR*2)
#define STAGEB (4*TILEB)
#define HSMEM (2*STAGEB)

__global__ void __launch_bounds__(256, 1) hgemm(
    const __half* __restrict__ Ahi, const __half* __restrict__ Alo,
    const __half* __restrict__ Bhi, const __half* __restrict__ Blo,
    const float* __restrict__ bias,
    float* __restrict__ Cf, __half* __restrict__ Chi, __half* __restrict__ Clo,
    int M, int Ntot, int K, int doRelu)
{
    extern __shared__ char sm[];
    const int tid  = threadIdx.x;
    const int lane = tid & 31;
    const int w    = tid >> 5;
    const int wm   = w & 3;
    const int wn   = w >> 2;
    const int bx = blockIdx.x, by = blockIdx.y;

    const uint32_t smb = smem_u32(sm);

    const __half* tb[4];
    tb[0] = Ahi + (size_t)(by*BM) * K;
    tb[1] = Alo + (size_t)(by*BM) * K;
    tb[2] = Bhi + (size_t)(bx*BN) * K;
    tb[3] = Blo + (size_t)(bx*BN) * K;

    float acc[2][8][4];
#pragma unroll
    for (int i = 0; i < 2; i++)
#pragma unroll
        for (int j = 0; j < 8; j++)
#pragma unroll
            for (int q = 0; q < 4; q++) acc[i][j][q] = 0.f;

    auto loadstage = [&](int st, int k0){
        uint32_t sb = smb + st * STAGEB;
#pragma unroll
        for (int m = 0; m < 4; m++) {
#pragma unroll
            for (int i = 0; i < 2; i++) {
                int idx = i*256 + tid;
                int row = idx >> 2, c4 = idx & 3;
                uint32_t dst = sb + m*TILEB + row*(SSTR*2) + c4*16;
                const __half* src = tb[m] + (size_t)row * K + k0 + c4*8;
                cpasync16(dst, src);
            }
        }
    };

    auto compute = [&](int st){
        uint32_t sA = smb + st * STAGEB;
        uint32_t sB = sA + 2*TILEB;
#pragma unroll
        for (int ks = 0; ks < 2; ks++) {
            uint32_t ahi[2][4], alo[2][4];
#pragma unroll
            for (int mt = 0; mt < 2; mt++) {
                int row  = wm*32 + mt*16 + (lane & 15);
                int koff = ks*16 + ((lane >> 4) << 3);
                uint32_t ad = sA + row*(SSTR*2) + koff*2;
                ldsm4(ahi[mt], ad);
                ldsm4(alo[mt], ad + TILEB);
            }
            uint32_t bhi[8][2], blo[8][2];
#pragma unroll
            for (int g = 0; g < 4; g++) {
                int nrow = wn*64 + g*16 + (lane & 7) + ((lane >> 4) << 3);
                int koff = ks*16 + (((lane >> 3) & 1) << 3);
                uint32_t bd = sB + nrow*(SSTR*2) + koff*2;
                uint32_t t4[4];
                ldsm4(t4, bd);
                bhi[2*g][0] = t4[0]; bhi[2*g][1] = t4[1];
                bhi[2*g+1][0] = t4[2]; bhi[2*g+1][1] = t4[3];
                ldsm4(t4, bd + TILEB);
                blo[2*g][0] = t4[0]; blo[2*g][1] = t4[1];
                blo[2*g+1][0] = t4[2]; blo[2*g+1][1] = t4[3];
            }
#pragma unroll
            for (int mt = 0; mt < 2; mt++)
#pragma unroll
                for (int nt = 0; nt < 8; nt++) {
                    mma16816(acc[mt][nt], ahi[mt], bhi[nt]);
                    mma16816(acc[mt][nt], ahi[mt], blo[nt]);
                    mma16816(acc[mt][nt], alo[mt], bhi[nt]);
                }
        }
    };

    const int NC = K / BK;
    loadstage(0, 0); CP_COMMIT();
    CP_WAIT0(); __syncthreads();
    for (int c = 0; c < NC; c++) {
        int cur = c & 1;
        if (c + 1 < NC) { loadstage(cur ^ 1, (c + 1) * BK); CP_COMMIT(); }
        compute(cur);
        if (c + 1 < NC) { CP_WAIT0(); __syncthreads(); }
    }

#pragma unroll
    for (int mt = 0; mt < 2; mt++) {
#pragma unroll
        for (int nt = 0; nt < 8; nt++) {
            int r0 = by*BM + wm*32 + mt*16 + (lane >> 2);
            int c0 = bx*BN + wn*64 + nt*8 + (lane & 3)*2;
            float b0 = bias ? bias[c0]   : 0.f;
            float b1 = bias ? bias[c0+1] : 0.f;
            float v0 = acc[mt][nt][0] + b0;
            float v1 = acc[mt][nt][1] + b1;
            float v2 = acc[mt][nt][2] + b0;
            float v3 = acc[mt][nt][3] + b1;
            if (doRelu) {
                v0 = fmaxf(v0, 0.f); v1 = fmaxf(v1, 0.f);
                v2 = fmaxf(v2, 0.f); v3 = fmaxf(v3, 0.f);
            }
            if (Cf) {
                *(float2*)(Cf + (size_t)r0 * Ntot + c0)       = make_float2(v0, v1);
                *(float2*)(Cf + (size_t)(r0+8) * Ntot + c0)   = make_float2(v2, v3);
            } else {
                __half h0 = __float2half_rn(v0), h1 = __float2half_rn(v1);
                __half h2 = __float2half_rn(v2), h3 = __float2half_rn(v3);
                __half l0 = __float2half_rn(v0 - __half2float(h0));
                __half l1 = __float2half_rn(v1 - __half2float(h1));
                __half l2 = __float2half_rn(v2 - __half2float(h2));
                __half l3 = __float2half_rn(v3 - __half2float(h3));
                *(__half2*)(Chi + (size_t)r0 * Ntot + c0)     = __halves2half2(h0, h1);
                *(__half2*)(Chi + (size_t)(r0+8) * Ntot + c0) = __halves2half2(h2, h3);
                *(__half2*)(Clo + (size_t)r0 * Ntot + c0)     = __halves2half2(l0, l1);
                *(__half2*)(Clo + (size_t)(r0+8) * Ntot + c0) = __halves2half2(l2, l3);
            }
        }
    }
}

// ---------------- fp32 -> fp16 hi/lo split ----------------
__global__ void split_k(const float* __restrict__ in, __half* __restrict__ hi,
                        __half* __restrict__ lo, int n)
{
    int i = (blockIdx.x * 256 + threadIdx.x) * 4;
    if (i >= n) return;
    float4 v = *(const float4*)(in + i);
    __half h0 = __float2half_rn(v.x), h1 = __float2half_rn(v.y);
    __half h2 = __float2half_rn(v.z), h3 = __float2half_rn(v.w);
    *(__half2*)(hi + i)     = __halves2half2(h0, h1);
    *(__half2*)(hi + i + 2) = __halves2half2(h2, h3);
    __half l0 = __float2half_rn(v.x - __half2float(h0));
    __half l1 = __float2half_rn(v.y - __half2float(h1));
    __half l2 = __float2half_rn(v.z - __half2float(h2));
    __half l3 = __float2half_rn(v.w - __half2float(h3));
    *(__half2*)(lo + i)     = __halves2half2(l0, l1);
    *(__half2*)(lo + i + 2) = __halves2half2(l2, l3);
}

// ---------------- transpose [R,C] fp32 -> [C,R] fp16 hi/lo ----------------
__global__ void transpose_split_k(const float* __restrict__ in,
                                  __half* __restrict__ hi, __half* __restrict__ lo,
                                  int R, int C)
{
    __shared__ float t[32][33];
    int c0 = blockIdx.x * 32, r0 = blockIdx.y * 32;
    int x = threadIdx.x, y = threadIdx.y;
    for (int i = y; i < 32; i += 8) t[i][x] = in[(size_t)(r0 + i) * C + c0 + x];
    __syncthreads();
    for (int i = y; i < 32; i += 8) {
        float v = t[x][i];
        __half h = __float2half_rn(v);
        __half l = __float2half_rn(v - __half2float(h));
        size_t o = (size_t)(c0 + i) * R + r0 + x;
        hi[o] = h; lo[o] = l;
    }
}

// ---------------- risk counter reset ----------------
__global__ void zero_nrisk_k() { if (threadIdx.x == 0) d_nrisk = 0; }

// ---------------- flag rows with near-tie decisions ----------------
__global__ void flag_k()
{
    int row = blockIdx.x * 8 + threadIdx.y;
    int lane = threadIdx.x;
    const float* lg = d_logits + (size_t)row * KK;
    float v[8];
    float best = -3.4e38f; int bi = 0;
#pragma unroll
    for (int t = 0; t < 8; t++) {
        int id = lane + t*32;
        v[t] = lg[id];
        if (v[t] > best) { best = v[t]; bi = id; }
    }
#pragma unroll
    for (int off = 16; off > 0; off >>= 1) {
        float ov = __shfl_down_sync(0xffffffffu, best, off);
        int   oi = __shfl_down_sync(0xffffffffu, bi,   off);
        if (ov > best || (ov == best && oi < bi)) { best = ov; bi = oi; }
    }
    best = __shfl_sync(0xffffffffu, best, 0);
    bi   = __shfl_sync(0xffffffffu, bi,   0);
    float second = -3.4e38f;
    bool riskm = false;
#pragma unroll
    for (int t = 0; t < 8; t++) {
        int id = lane + t*32;
        if (id != bi) {
            second = fmaxf(second, v[t]);
            if (fabsf(v[t] + 0.1f - best) < RISK_EPS) riskm = true;
        }
    }
#pragma unroll
    for (int off = 16; off > 0; off >>= 1)
        second = fmaxf(second, __shfl_down_sync(0xffffffffu, second, off));
    bool risk = __any_sync(0xffffffffu, riskm);
    if (lane == 0) {
        if ((best - second) < RISK_EPS || risk) {
            int slot = atomicAdd(&d_nrisk, 1);
            if (slot < MAXR) d_risk[slot] = row;
        }
    }
}

// ---------------- gather flagged x rows into compact Xr (zero-padded) ----------------
__global__ void gather_x_k(const float* __restrict__ x)
{
    int nr = d_nrisk; if (nr > MAXR) nr = MAXR;
    int nrp = (nr + 127) & ~127;
    int r = blockIdx.x;
    if (r >= nrp) return;
    float4 v = make_float4(0.f, 0.f, 0.f, 0.f);
    if (r < nr) {
        int src = d_risk[r];
        v = ((const float4*)(x + (size_t)src * DIN))[threadIdx.x];
    }
    ((float4*)(d_Xr + (size_t)r * DIN))[threadIdx.x] = v;
}

// ---------------- scatter exact logits back ----------------
__global__ void scatter_logits_k()
{
    int nr = d_nrisk; if (nr > MAXR) nr = MAXR;
    int r = blockIdx.x;
    if (r >= nr) return;
    int dst = d_risk[r];
    d_logits[(size_t)dst * KK + threadIdx.x] = d_Lr[(size_t)r * KK + threadIdx.x];
}

// =======================================================================
// packed f32x2 GEMM (table GEMMs — known-correct) + dynamic-M variant
// =======================================================================
__device__ __forceinline__ unsigned long long pack2f(float lo, float hi){
    unsigned long long r; asm("mov.b64 %0, {%1,%2};" : "=l"(r) : "f"(lo), "f"(hi)); return r;
}
__device__ __forceinline__ void unpack2f(unsigned long long v, float& lo, float& hi){
    asm("mov.b64 {%0,%1}, %2;" : "=f"(lo), "=f"(hi) : "l"(v));
}
__device__ __forceinline__ void ffma2(unsigned long long& d, unsigned long long a, unsigned long long b){
    asm("fma.rn.f32x2 %0, %1, %2, %0;" : "+l"(d) : "l"(a), "l"(b));
}

// core body shared by both variants
__device__ __forceinline__ void gemm128_body(
    const float* __restrict__ A, const float* __restrict__ B,
    const float* __restrict__ bias, float* __restrict__ C,
    int M, int N, int Kd, float alpha, int doRelu,
    int bx, int by, int nz, int bz)
{
    __shared__ float As[16][128];
    __shared__ float Bs[16][128];
    const int tid = threadIdx.x;
    const int Kper = Kd / nz;
    const int kBase = bz * Kper;
    const bool partial = (nz > 1);
    if (partial) C += (size_t)bz * (size_t)M * N;

    const int aRow = tid >> 2;
    const int aCol = (tid & 3) << 2;
    const int bRow = tid >> 5;
    const int bCol = (tid & 31) << 2;
    const int tx = tid & 15, ty = tid >> 4;

    unsigned long long acc[4][8];
#pragma unroll
    for (int i = 0; i < 4; i++)
#pragma unroll
        for (int j = 0; j < 8; j++) acc[i][j] = 0ull;

    const float* Abase = A + (size_t)(by*128)*Kd + kBase;
    const float* Bbase = B + (size_t)kBase*N + bx*128;

    for (int k0 = 0; k0 < Kper; k0 += 16) {
#pragma unroll
        for (int i = 0; i < 2; i++) {
            int r = aRow + i*64;
            float4 v = *(const float4*)(Abase + (size_t)r*Kd + k0 + aCol);
            As[aCol+0][r] = v.x; As[aCol+1][r] = v.y;
            As[aCol+2][r] = v.z; As[aCol+3][r] = v.w;
        }
#pragma unroll
        for (int i = 0; i < 2; i++) {
            int r = bRow + i*8;
            *(float4*)&Bs[r][bCol] = *(const float4*)(Bbase + (size_t)(k0+r)*N + bCol);
        }
        __syncthreads();
#pragma unroll
        for (int kk = 0; kk < 16; kk++) {
            float4 av0 = *(const float4*)&As[kk][ty*8];
            float4 av1 = *(const float4*)&As[kk][ty*8+4];
            float4 bv0 = *(const float4*)&Bs[kk][tx*8];
            float4 bv1 = *(const float4*)&Bs[kk][tx*8+4];
            unsigned long long a2[4] = {
                pack2f(av0.x, av0.y), pack2f(av0.z, av0.w),
                pack2f(av1.x, av1.y), pack2f(av1.z, av1.w)};
            float bf[8] = {bv0.x,bv0.y,bv0.z,bv0.w,bv1.x,bv1.y,bv1.z,bv1.w};
#pragma unroll
            for (int j = 0; j < 8; j++) {
                unsigned long long bd = pack2f(bf[j], bf[j]);
#pragma unroll
                for (int i = 0; i < 4; i++) ffma2(acc[i][j], a2[i], bd);
            }
        }
        __syncthreads();
    }

    float out[8][8];
#pragma unroll
    for (int i2 = 0; i2 < 4; i2++)
#pragma unroll
        for (int j = 0; j < 8; j++)
            unpack2f(acc[i2][j], out[2*i2][j], out[2*i2+1][j]);

    float bl[8];
#pragma unroll
    for (int j = 0; j < 8; j++) bl[j] = 0.f;
    if (bias != nullptr && !partial) {
#pragma unroll
        for (int j = 0; j < 8; j++) bl[j] = bias[bx*128 + tx*8 + j];
    }

#pragma unroll
    for (int i = 0; i < 8; i++) {
        int row = by*128 + ty*8 + i;
        float* Crow = C + (size_t)row*N + bx*128 + tx*8;
        float vals[8];
#pragma unroll
        for (int j = 0; j < 8; j++) {
            float v = out[i][j];
            if (!partial) {
                v = v * alpha + bl[j];
                if (doRelu) v = fmaxf(v, 0.f);
            }
            vals[j] = v;
        }
        *(float4*)(Crow + 0) = make_float4(vals[0], vals[1], vals[2], vals[3]);
        *(float4*)(Crow + 4) = make_float4(vals[4], vals[5], vals[6], vals[7]);
    }
}

__global__ void __launch_bounds__(256, 2) gemm128(
    const float* __restrict__ A, const float* __restrict__ B,
    const float* __restrict__ bias, float* __restrict__ C,
    int M, int N, int Kd, float alpha, int doRelu)
{
    gemm128_body(A, B, bias, C, M, N, Kd, alpha, doRelu,
                 blockIdx.x, blockIdx.y, gridDim.z, blockIdx.z);
}

// dynamic-M: row-tile count derived from d_nrisk; unused tiles exit
__global__ void __launch_bounds__(256, 2) gemm128_dyn(
    const float* __restrict__ A, const float* __restrict__ B,
    const float* __restrict__ bias, float* __restrict__ C,
    int N, int Kd, int doRelu)
{
    int nr = d_nrisk; if (nr > MAXR) nr = MAXR;
    int nrp = (nr + 127) & ~127;
    if (blockIdx.y * 128 >= nrp) return;
    gemm128_body(A, B, bias, C, nrp, N, Kd, 1.f, doRelu,
                 blockIdx.x, blockIdx.y, 1, 0);
}

// ---------------- per-row argmax + keep-mask ----------------
__global__ void argmax_keep_k()
{
    int row = blockIdx.x * 8 + threadIdx.y;
    int lane = threadIdx.x;
    const float* lg = d_logits + (size_t)row * KK;
    float v[8];
    float best = -3.4e38f; int bi = 0;
#pragma unroll
    for (int t = 0; t < 8; t++) {
        int id = lane + t*32;
        v[t] = lg[id];
        if (v[t] > best) { best = v[t]; bi = id; }
    }
#pragma unroll
    for (int off = 16; off > 0; off >>= 1) {
        float ov = __shfl_down_sync(0xffffffffu, best, off);
        int   oi = __shfl_down_sync(0xffffffffu, bi,   off);
        if (ov > best || (ov == best && oi < bi)) { best = ov; bi = oi; }
    }
    best = __shfl_sync(0xffffffffu, best, 0);
    bi   = __shfl_sync(0xffffffffu, bi,   0);
    if (lane == 0) d_a0[row] = bi;
#pragma unroll
    for (int t = 0; t < 8; t++) {
        int id = lane + t*32;
        float adj = v[t] + 0.1f;
        bool k = (adj > best) || (adj == best && id < bi) || (id == bi);
        unsigned bw = __ballot_sync(0xffffffffu, k);
        if (lane == t) d_keep[(size_t)row*8 + t] = bw;
    }
}

// ---------------- segmented parallel mode scan ----------------
__global__ void seg_pre_k()
{
    __shared__ unsigned sm_m[SEGL*8];
    __shared__ int sm_a0[SEGL];
    __shared__ int sm_e[SEGL];
    int blk = blockIdx.x;
    int tid = threadIdx.x;
    size_t rbase = (size_t)blk * SEGL;
    for (int i = tid; i < SEGL*8; i += 256) sm_m[i] = d_keep[rbase*8 + i];
    for (int i = tid; i < SEGL; i += 256)   sm_a0[i] = d_a0[rbase + i];
    __syncthreads();
    if (tid < SEGL) {
        int v = sm_a0[tid];
        for (int s = tid + 1; s < SEGL; s++) {
            unsigned w = sm_m[s*8 + (v >> 5)];
            if (!((w >> (v & 31)) & 1u)) v = sm_a0[s];
        }
        sm_e[tid] = v;
    }
    __syncthreads();
    int p = tid;
    int ex = p;
    for (int s = 0; s < SEGL; s++) {
        unsigned w = sm_m[s*8 + (p >> 5)];
        if (!((w >> (p & 31)) & 1u)) { ex = sm_e[s]; break; }
    }
    d_exitv[blk * KK + p] = ex;
}

__global__ void chain_k(const float* __restrict__ prevm)
{
    int b = threadIdx.x;
    if (b < Bb) {
        int p = 0;
        for (int k = 0; k < KK; k++)
            if (prevm[b*KK + k] > 0.5f) { p = k; break; }
        for (int s = 0; s < NSEG; s++) {
            d_entry[b*NSEG + s] = p;
            p = d_exitv[(b*NSEG + s) * KK + p];
        }
    }
}

__global__ void seg_replay_k()
{
    __shared__ unsigned sm_m[SEGL*8];
    __shared__ int sm_a0[SEGL];
    __shared__ int sm_md[SEGL];
    int blk = blockIdx.x;
    int tid = threadIdx.x;
    size_t rbase = (size_t)blk * SEGL;
    for (int i = tid; i < SEGL*8; i += 256) sm_m[i] = d_keep[rbase*8 + i];
    for (int i = tid; i < SEGL; i += 256)   sm_a0[i] = d_a0[rbase + i];
    __syncthreads();
    if (tid == 0) {
        int p = d_entry[blk];
        for (int s = 0; s < SEGL; s++) {
            unsigned w = sm_m[s*8 + (p >> 5)];
            p = ((w >> (p & 31)) & 1u) ? p : sm_a0[s];
            sm_md[s] = p;
        }
    }
    __syncthreads();
    if (tid < SEGL) d_mode[rbase + tid] = sm_md[tid];
}

// ---------------- l2-normalize rows (optionally transposed output) ----------------
__global__ void l2norm_k(const float* __restrict__ in, float* __restrict__ out,
                         int nrows, int transpose)
{
    int row = blockIdx.x * 8 + threadIdx.y;
    if (row >= nrows) return;
    int lane = threadIdx.x;
    const float* p = in + (size_t)row * DM;
    float v[16]; float ss = 0.f;
#pragma unroll
    for (int t = 0; t < 16; t++) { v[t] = p[lane + t*32]; ss += v[t]*v[t]; }
#pragma unroll
    for (int off = 16; off > 0; off >>= 1) ss += __shfl_xor_sync(0xffffffffu, ss, off);
    float rn = 1.f / fmaxf(sqrtf(ss), 1e-12f);
    if (transpose) {
#pragma unroll
        for (int t = 0; t < 16; t++)
            out[(size_t)(lane + t*32) * BANKN + row] = v[t] * rn;
    } else {
#pragma unroll
        for (int t = 0; t < 16; t++)
            out[(size_t)row * DM + lane + t*32] = v[t] * rn;
    }
}

// ---------------- masked softmax over bank slots ----------------
__global__ void softmax_k(const float* __restrict__ used)
{
    int row = blockIdx.x;
    float* s = d_scores + (size_t)row * BANKN;
    int tid = threadIdx.x;  // 256
    __shared__ float red[256];
    float v[16];
    float mx = -3.4e38f;
#pragma unroll
    for (int t = 0; t < 16; t++) {
        int c = tid + t*256;
        float x = s[c];
        x = (used[c] > 0.5f) ? x : -1e30f;
        v[t] = x; mx = fmaxf(mx, x);
    }
    red[tid] = mx; __syncthreads();
    for (int o = 128; o > 0; o >>= 1) { if (tid < o) red[tid] = fmaxf(red[tid], red[tid+o]); __syncthreads(); }
    mx = red[0]; __syncthreads();
    float sum = 0.f;
#pragma unroll
    for (int t = 0; t < 16; t++) { v[t] = expf(v[t] - mx); sum += v[t]; }
    red[tid] = sum; __syncthreads();
    for (int o = 128; o > 0; o >>= 1) { if (tid < o) red[tid] += red[tid+o]; __syncthreads(); }
    float inv = 1.f / red[0];
#pragma unroll
    for (int t = 0; t < 16; t++) s[tid + t*256] = v[t] * inv;
}

// ---------------- reduce split-K partials ----------------
__global__ void reduce_bank_k()
{
    int i = blockIdx.x * 256 + threadIdx.x;
    float s = 0.f;
#pragma unroll
    for (int z = 0; z < 8; z++) s += d_part[(size_t)z*KK*DM + i];
    d_bankt[i] = s;
}

// ---------------- rms-norm with g ----------------
__global__ void rms_k(const float* __restrict__ Mw, const float* __restrict__ g)
{
    int k = blockIdx.x;
    int tid = threadIdx.x;  // 128
    __shared__ float red[128];
    float r[4]; float ss = 0.f;
#pragma unroll
    for (int t = 0; t < 4; t++) {
        int c = tid + t*128;
        r[t] = Mw[(size_t)k*DM + c] + d_bankt[(size_t)k*DM + c];
        ss += r[t]*r[t];
    }
    red[tid] = ss; __syncthreads();
    for (int o = 64; o > 0; o >>= 1) { if (tid < o) red[tid] += red[tid+o]; __syncthreads(); }
    float mean = red[0] / (float)DM;
    float sc = 1.f / sqrtf(mean + 1e-6f);
#pragma unroll
    for (int t = 0; t < 4; t++) {
        int c = tid + t*128;
        d_rn[(size_t)k*DM + c] = r[t] * g[c] * sc;
    }
}

// ---------------- gather y rows + scatter one-hot modes ----------------
__global__ void assemble_k(float* __restrict__ y, float* __restrict__ modes, int writeModes)
{
    int row = blockIdx.x;
    int t = threadIdx.x;  // 256
    int m = d_mode[row];
    float4 v = ((const float4*)(d_ytab + (size_t)m * DOUT))[t];
    ((float4*)(y + (size_t)row * DOUT))[t] = v;
    if (writeModes)
        modes[(size_t)row * KK + t] = (t == m) ? 1.f : 0.f;
}

// ---------------- launch ----------------
extern "C" void kernel_launch(void* const* d_in, const int* in_sizes, int n_in,
                              void* d_out, int out_size)
{
    const float* x     = (const float*)d_in[0];
    const float* prevm = (const float*)d_in[1];
    const float* Wtr_w = (const float*)d_in[2];
    const float* Wtr_b = (const float*)d_in[3];
    const float* Wms_w = (const float*)d_in[4];
    const float* Wms_b = (const float*)d_in[5];
    const float* Mw    = (const float*)d_in[6];
    const float* g     = (const float*)d_in[7];
    const float* Wrd_w = (const float*)d_in[8];
    const float* Wrd_b = (const float*)d_in[9];
    const float* bkeys = (const float*)d_in[10];
    const float* bvals = (const float*)d_in[11];
    const float* bused = (const float*)d_in[12];

    float* y = (float*)d_out;
    int writeModes = (out_size >= (int)((size_t)RR*DOUT + (size_t)RR*KK)) ? 1 : 0;
    float* modes = y + (size_t)RR * DOUT;

    void *pxhi, *pxlo, *phhi, *phlo, *pWthi, *pWtlo, *pWmhi, *pWmlo;
    void *plog, *pknT, *pqn, *pscores, *ppart, *prn, *pytab, *pXr, *pHr, *pLr;
    cudaGetSymbolAddress(&pxhi, d_xhi);
    cudaGetSymbolAddress(&pxlo, d_xlo);
    cudaGetSymbolAddress(&phhi, d_hhi);
    cudaGetSymbolAddress(&phlo, d_hlo);
    cudaGetSymbolAddress(&pWthi, d_WtrThi);
    cudaGetSymbolAddress(&pWtlo, d_WtrTlo);
    cudaGetSymbolAddress(&pWmhi, d_WmsThi);
    cudaGetSymbolAddress(&pWmlo, d_WmsTlo);
    cudaGetSymbolAddress(&plog, d_logits);
    cudaGetSymbolAddress(&pknT, d_knT);
    cudaGetSymbolAddress(&pqn, d_qn);
    cudaGetSymbolAddress(&pscores, d_scores);
    cudaGetSymbolAddress(&ppart, d_part);
    cudaGetSymbolAddress(&prn, d_rn);
    cudaGetSymbolAddress(&pytab, d_ytab);
    cudaGetSymbolAddress(&pXr, d_Xr);
    cudaGetSymbolAddress(&pHr, d_Hr);
    cudaGetSymbolAddress(&pLr, d_Lr);

    cudaFuncSetAttribute(hgemm, cudaFuncAttributeMaxDynamicSharedMemorySize, HSMEM);

    // operand prep: split x, transpose+split weights
    split_k<<<(RR*DIN)/(256*4), 256>>>(x, (__half*)pxhi, (__half*)pxlo, RR*DIN);
    transpose_split_k<<<dim3(HH/32, DIN/32), dim3(32,8)>>>(Wtr_w, (__half*)pWthi, (__half*)pWtlo, DIN, HH);
    transpose_split_k<<<dim3(KK/32, HH/32), dim3(32,8)>>>(Wms_w, (__half*)pWmhi, (__half*)pWmlo, HH, KK);

    // GEMM1: h = relu(x @ Wtr + b) -> hi/lo fp16   [16384,2048]
    hgemm<<<dim3(HH/BN, RR/BM), 256, HSMEM>>>(
        (const __half*)pxhi, (const __half*)pxlo,
        (const __half*)pWthi, (const __half*)pWtlo,
        Wtr_b, nullptr, (__half*)phhi, (__half*)phlo, RR, HH, DIN, 1);

    // GEMM2: logits = h @ Wms + b -> fp32          [16384,256]
    hgemm<<<dim3(KK/BN, RR/BM), 256, HSMEM>>>(
        (const __half*)phhi, (const __half*)phlo,
        (const __half*)pWmhi, (const __half*)pWmlo,
        Wms_b, (float*)plog, nullptr, nullptr, RR, KK, HH, 0);

    // near-tie detection + weight-stationary exact fp32 recompute
    zero_nrisk_k<<<1, 32>>>();
    flag_k<<<RR/8, dim3(32,8)>>>();
    gather_x_k<<<MAXR, 256>>>(x);
    // Hr = relu(Xr @ Wtr + b) : B = Wtr_w [DIN,HH] row-major (K-major for gemm128)
    gemm128_dyn<<<dim3(HH/128, MAXR/128), 256>>>((const float*)pXr, Wtr_w, Wtr_b,
                                                 (float*)pHr, HH, DIN, 1);
    // Lr = Hr @ Wms + b
    gemm128_dyn<<<dim3(KK/128, MAXR/128), 256>>>((const float*)pHr, Wms_w, Wms_b,
                                                 (float*)pLr, KK, HH, 0);
    scatter_logits_k<<<MAXR, 256>>>();

    // per-row argmax + keep masks (reads fixed logits)
    argmax_keep_k<<<RR/8, dim3(32,8)>>>();
    // segmented parallel mode scan
    seg_pre_k<<<Bb*NSEG, 256>>>();
    chain_k<<<1, 32>>>(prevm);
    seg_replay_k<<<Bb*NSEG, 256>>>();

    // --- mode table construction (tiny; proven fp32 path) ---
    l2norm_k<<<BANKN/8, dim3(32,8)>>>(bkeys, (float*)pknT, BANKN, 1);
    l2norm_k<<<KK/8,    dim3(32,8)>>>(Mw,    (float*)pqn,  KK,    0);
    gemm128<<<dim3(BANKN/128, KK/128), 256>>>((const float*)pqn, (const float*)pknT, nullptr,
                                              (float*)pscores, KK, BANKN, DM, 4.0f, 0);
    softmax_k<<<KK, 256>>>(bused);
    gemm128<<<dim3(DM/128, KK/128, 8), 256>>>((const float*)pscores, bvals, nullptr,
                                              (float*)ppart, KK, DM, BANKN, 1.f, 0);
    reduce_bank_k<<<(KK*DM)/256, 256>>>();
    rms_k<<<KK, 128>>>(Mw, g);
    gemm128<<<dim3(DOUT/128, KK/128), 256>>>((const float*)prn, Wrd_w, Wrd_b,
                                             (float*)pytab, KK, DOUT, DM, 1.f, 0);

    // gather + one-hot scatter
    assemble_k<<<RR, 256>>>(y, modes, writeModes);
}